// round 10
// baseline (speedup 1.0000x reference)
#include <cuda_runtime.h>
#include <cuda_bf16.h>
#include <cstddef>
#include <cstdint>

// Problem constants (B=4096, n=512, m=1024)
#define Bsz 4096
#define Nn  512
#define Mm  1024
#define STEPC 0.01f
#define TOLV 1e-5f

// ---- tensor tile config ----
#define TM 128
#define TN 256
#define KC 64
#define TILEA_B 16384          // 128x64 bf16 tile bytes
#define TILEB_B 32768          // 256x64 bf16 tile bytes
#define OFF_ALO 16384
#define OFF_BHI 32768
#define OFF_BLO 65536
#define STG_SZ  98304          // 96 KB per stage
#define DSMEM   (2 * STG_SZ + 1024)

#if defined(__CUDA_ARCH__) && defined(__CUDA_ARCH_FEAT_SM103_ALL)
#define HAS_TCGEN05 1
#else
#define HAS_TCGEN05 0
#endif

// ---------------- device scratch (allocation-free) ----------------
__device__ __align__(128) float g_c[(size_t)Bsz * Mm];
__device__ __align__(128) float g_msk[(size_t)Bsz * Mm];
__device__ __align__(128) float g_act[(size_t)Bsz * Mm];
__device__ __align__(128) __nv_bfloat16 g_AAi_h[Mm * Nn];   // A as A-image [8][8]
__device__ __align__(128) __nv_bfloat16 g_AAi_l[Mm * Nn];
__device__ __align__(128) __nv_bfloat16 g_ABi_h[Mm * Nn];   // A as B-image [4][8]
__device__ __align__(128) __nv_bfloat16 g_ABi_l[Mm * Nn];
__device__ __align__(128) __nv_bfloat16 g_ATi_h[Nn * Mm];   // A^T as B-image [2][16]
__device__ __align__(128) __nv_bfloat16 g_ATi_l[Nn * Mm];
__device__ __align__(128) __nv_bfloat16 g_xu_h[(size_t)Bsz * Nn];
__device__ __align__(128) __nv_bfloat16 g_xu_l[(size_t)Bsz * Nn];
__device__ __align__(128) __nv_bfloat16 g_u_h[(size_t)Bsz * Nn];
__device__ __align__(128) __nv_bfloat16 g_u_l[(size_t)Bsz * Nn];
__device__ __align__(128) __nv_bfloat16 g_z_h[(size_t)Bsz * Nn];
__device__ __align__(128) __nv_bfloat16 g_z_l[(size_t)Bsz * Nn];
// Q as B-image [4 nb][16 ch][256x64, 32 KB]
__device__ __align__(128) __nv_bfloat16 g_Qhi[Mm * Mm];
__device__ __align__(128) __nv_bfloat16 g_Qlo[Mm * Mm];
__device__ __align__(128) __nv_bfloat16 g_lAhi[(size_t)Bsz * Mm]; // lam A-images [32][16]
__device__ __align__(128) __nv_bfloat16 g_lAlo[(size_t)Bsz * Mm];
__device__ __align__(128) __nv_bfloat16 g_lBhi[(size_t)Bsz * Mm];
__device__ __align__(128) __nv_bfloat16 g_lBlo[(size_t)Bsz * Mm];

// ---------------- helpers ----------------
__device__ __forceinline__ uint32_t s2u(const void* p) {
    uint32_t a;
    asm("{ .reg .u64 t; cvta.to.shared.u64 t, %1; cvt.u32.u64 %0, t; }"
        : "=r"(a) : "l"(p));
    return a;
}
__device__ __forceinline__ uint32_t swz(uint32_t off) {
    return off ^ ((off >> 3) & 0x70);
}
__device__ __forceinline__ void mbar_init(uint32_t a, uint32_t cnt) {
    asm volatile("mbarrier.init.shared.b64 [%0], %1;" :: "r"(a), "r"(cnt) : "memory");
}
__device__ __forceinline__ void mbar_arrive_tx(uint32_t a, uint32_t bytes) {
    asm volatile("mbarrier.arrive.expect_tx.shared.b64 _, [%0], %1;"
                 :: "r"(a), "r"(bytes) : "memory");
}
__device__ __forceinline__ void mbar_tx_only(uint32_t a, uint32_t bytes) {
    asm volatile("mbarrier.expect_tx.shared.b64 [%0], %1;"
                 :: "r"(a), "r"(bytes) : "memory");
}
__device__ __forceinline__ void mbar_wait(uint32_t a, uint32_t phase) {
    uint32_t done = 0;
    while (!done) {
        asm volatile(
            "{ .reg .pred p; mbarrier.try_wait.parity.shared.b64 p, [%1], %2; "
            "selp.b32 %0, 1, 0, p; }"
            : "=r"(done) : "r"(a), "r"(phase) : "memory");
    }
}
__device__ __forceinline__ void bulk_g2s(uint32_t dst, const void* src,
                                         uint32_t bytes, uint32_t mbar) {
    asm volatile(
        "cp.async.bulk.shared::cluster.global.mbarrier::complete_tx::bytes "
        "[%0], [%1], %2, [%3];"
        :: "r"(dst), "l"(src), "r"(bytes), "r"(mbar) : "memory");
}
__device__ __forceinline__ uint64_t mkdesc(uint32_t addr) {
    return ((uint64_t)2 << 61) | ((uint64_t)1 << 46) | ((uint64_t)64 << 32)
         | ((uint64_t)1 << 16) | ((addr >> 4) & 0x3FFF);
}
#define GEMM_IDESC ((1u<<4) | (1u<<7) | (1u<<10) | ((TN/8)<<17) | ((128/16)<<24))

__device__ __forceinline__ float bfbits2f(uint16_t u) {
    __nv_bfloat16_raw r; r.x = u;
    return __bfloat162float(__nv_bfloat16(r));
}
__device__ __forceinline__ uint16_t f2bfbits(float f) {
    __nv_bfloat16 h = __float2bfloat16(f);
    __nv_bfloat16_raw r = (__nv_bfloat16_raw)h;
    return r.x;
}

#if HAS_TCGEN05
__device__ __forceinline__ void mma_f16_ss(uint32_t d, uint64_t a, uint64_t b,
                                           uint32_t idesc, uint32_t en) {
    asm volatile(
        "{\n\t.reg .pred p;\n\tsetp.ne.u32 p, %5, 0;\n\t"
        "tcgen05.mma.cta_group::1.kind::f16 [%0], %1, %2, %3, {%4,%4,%4,%4}, p;\n\t}"
        :: "r"(d), "l"(a), "l"(b), "r"(idesc), "r"(0u), "r"(en) : "memory");
}
__device__ __forceinline__ void tc_commit(uint32_t mbar) {
    asm volatile(
        "tcgen05.commit.cta_group::1.mbarrier::arrive::one.shared::cluster.b64 [%0];"
        :: "r"(mbar) : "memory");
}
#define TC_ALLOC(sres, n) \
    asm volatile("tcgen05.alloc.cta_group::1.sync.aligned.shared::cta.b32 [%0], %1;" \
                 :: "r"(sres), "r"((uint32_t)(n)) : "memory")
#define TC_RELINQ() \
    asm volatile("tcgen05.relinquish_alloc_permit.cta_group::1.sync.aligned;")
#define TC_DEALLOC(t, n) \
    asm volatile("tcgen05.dealloc.cta_group::1.sync.aligned.b32 %0, %1;" :: "r"(t), "r"((uint32_t)(n)))
#define TC_FENCE_AFTER()  asm volatile("tcgen05.fence::after_thread_sync;" ::: "memory")
#define TC_FENCE_BEFORE() asm volatile("tcgen05.fence::before_thread_sync;" ::: "memory")
#define TC_WAIT_LD()      asm volatile("tcgen05.wait::ld.sync.aligned;" ::: "memory")
#define LDTM_X32(r, a) \
    asm volatile( \
        "tcgen05.ld.sync.aligned.32x32b.x32.b32 " \
        "{%0,%1,%2,%3,%4,%5,%6,%7,%8,%9,%10,%11,%12,%13,%14,%15," \
        "%16,%17,%18,%19,%20,%21,%22,%23,%24,%25,%26,%27,%28,%29,%30,%31}, [%32];" \
        : "=r"((r)[0]),"=r"((r)[1]),"=r"((r)[2]),"=r"((r)[3]), \
          "=r"((r)[4]),"=r"((r)[5]),"=r"((r)[6]),"=r"((r)[7]), \
          "=r"((r)[8]),"=r"((r)[9]),"=r"((r)[10]),"=r"((r)[11]), \
          "=r"((r)[12]),"=r"((r)[13]),"=r"((r)[14]),"=r"((r)[15]), \
          "=r"((r)[16]),"=r"((r)[17]),"=r"((r)[18]),"=r"((r)[19]), \
          "=r"((r)[20]),"=r"((r)[21]),"=r"((r)[22]),"=r"((r)[23]), \
          "=r"((r)[24]),"=r"((r)[25]),"=r"((r)[26]),"=r"((r)[27]), \
          "=r"((r)[28]),"=r"((r)[29]),"=r"((r)[30]),"=r"((r)[31]) \
        : "r"(a))
#endif  // HAS_TCGEN05

// ---------------------------------------------------------------------------
// Multi-iteration PGD in ONE launch, 4-CTA clusters.
//   Rows are iteration-independent; the 4 CTAs sharing a row-block (bn=0..3)
//   form a cluster and sync via barrier.cluster each iteration.
//   Q (B) prefetched pre-barrier (tx only); lam (A) loaded post-barrier.
// ---------------------------------------------------------------------------
__global__ void __launch_bounds__(256, 1) __cluster_dims__(4, 1, 1) pgd_cluster(
    __nv_bfloat16* __restrict__ lAhi, __nv_bfloat16* __restrict__ lAlo,
    __nv_bfloat16* __restrict__ lBhi, __nv_bfloat16* __restrict__ lBlo,
    const __nv_bfloat16* __restrict__ Qhi, const __nv_bfloat16* __restrict__ Qlo,
    const float* __restrict__ cc, const float* __restrict__ act,
    int nit, int masked)
{
#if HAS_TCGEN05
    extern __shared__ char draw[];
    const uint32_t dsm = (s2u(draw) + 1023u) & ~1023u;

    __shared__ uint32_t s_tmem;
    __shared__ __align__(8) uint64_t s_bar[5];   // f0,f1,e0,e1,done

    const int tid  = threadIdx.x;
    const int wid  = tid >> 5;
    const int lane = tid & 31;
    const int bm0  = blockIdx.y * TM;
    const int bn0  = blockIdx.x * TN;

    const uint32_t f0 = s2u(&s_bar[0]);
    const uint32_t f1 = s2u(&s_bar[1]);
    const uint32_t e0 = s2u(&s_bar[2]);
    const uint32_t e1 = s2u(&s_bar[3]);
    const uint32_t db = s2u(&s_bar[4]);

    if (wid == 0) TC_ALLOC(s2u(&s_tmem), 256);
    if (tid == 0) {
        mbar_init(f0, 1); mbar_init(f1, 1);
        mbar_init(e0, 1); mbar_init(e1, 1);
        mbar_init(db, 1);
    }
    __syncthreads();
    uint32_t tmem;
    asm volatile("ld.shared.b32 %0, [%1];" : "=r"(tmem) : "r"(s2u(&s_tmem)));

    const size_t yoffA = (size_t)blockIdx.y * 16 * TILEA_B;
    const char* bH = (const char*)Qhi + (size_t)blockIdx.x * 16 * TILEB_B;
    const char* bL = (const char*)Qlo + (size_t)blockIdx.x * 16 * TILEB_B;

    uint32_t phf0 = 0, phf1 = 0, phe0 = 0, phe1 = 0;

    // prologue: full A+B loads for chunks 0,1 of iteration 1 (A source = lA)
    if (tid == 0) {
        const char* aH = (const char*)lAhi + yoffA;
        const char* aL = (const char*)lAlo + yoffA;
#pragma unroll
        for (int ch = 0; ch < 2; ch++) {
            const uint32_t fb = ch ? f1 : f0;
            const uint32_t st = dsm + (uint32_t)ch * STG_SZ;
            mbar_arrive_tx(fb, STG_SZ);
            bulk_g2s(st,           aH + (size_t)ch * TILEA_B, TILEA_B, fb);
            bulk_g2s(st + OFF_ALO, aL + (size_t)ch * TILEA_B, TILEA_B, fb);
            bulk_g2s(st + OFF_BHI, bH + (size_t)ch * TILEB_B, TILEB_B, fb);
            bulk_g2s(st + OFF_BLO, bL + (size_t)ch * TILEB_B, TILEB_B, fb);
        }
    }

#pragma unroll 1
    for (int it = 1; it <= nit; it++) {
        const int odd = it & 1;
        const __nv_bfloat16* rdH = odd ? lAhi : lBhi;
        const __nv_bfloat16* rdL = odd ? lAlo : lBlo;
        __nv_bfloat16* wrH = odd ? lBhi : lAhi;
        __nv_bfloat16* wrL = odd ? lBlo : lAlo;

        // ---------- tid0: mainloop ----------
        if (tid == 0) {
            const char* aH = (const char*)rdH + yoffA;
            const char* aL = (const char*)rdL + yoffA;
#pragma unroll 1
            for (int ch = 0; ch < 16; ch++) {
                const int s = ch & 1;
                mbar_wait(s ? f1 : f0, s ? phf1 : phf0);
                if (s) phf1 ^= 1; else phf0 ^= 1;

                const uint32_t st = dsm + (uint32_t)s * STG_SZ;
                const uint64_t dah = mkdesc(st);
                const uint64_t dal = mkdesc(st + OFF_ALO);
                const uint64_t dbh = mkdesc(st + OFF_BHI);
                const uint64_t dbl = mkdesc(st + OFF_BLO);
#pragma unroll
                for (int ks = 0; ks < 4; ks++) {
                    mma_f16_ss(tmem, dah + ks * 2, dbh + ks * 2, GEMM_IDESC,
                               (ch == 0 && ks == 0) ? 0u : 1u);
                    mma_f16_ss(tmem, dah + ks * 2, dbl + ks * 2, GEMM_IDESC, 1u);
                    mma_f16_ss(tmem, dal + ks * 2, dbh + ks * 2, GEMM_IDESC, 1u);
                }
                tc_commit(s ? e1 : e0);

                if (ch < 14) {
                    mbar_wait(s ? e1 : e0, s ? phe1 : phe0);
                    if (s) phe1 ^= 1; else phe0 ^= 1;
                    const int nx = ch + 2;
                    const uint32_t fb = s ? f1 : f0;
                    mbar_arrive_tx(fb, STG_SZ);
                    bulk_g2s(st,           aH + (size_t)nx * TILEA_B, TILEA_B, fb);
                    bulk_g2s(st + OFF_ALO, aL + (size_t)nx * TILEA_B, TILEA_B, fb);
                    bulk_g2s(st + OFF_BHI, bH + (size_t)nx * TILEB_B, TILEB_B, fb);
                    bulk_g2s(st + OFF_BLO, bL + (size_t)nx * TILEB_B, TILEB_B, fb);
                }
            }
            tc_commit(db);

            if (it < nit) {
                // stages free once last two chunks' MMAs complete
                mbar_wait(e0, phe0); phe0 ^= 1;
                mbar_wait(e1, phe1); phe1 ^= 1;
                // prefetch next-iter B (Q) chunks 0,1 — tx only, no arrive
                mbar_tx_only(f0, 2 * TILEB_B);
                bulk_g2s(dsm + OFF_BHI,          bH,           TILEB_B, f0);
                bulk_g2s(dsm + OFF_BLO,          bL,           TILEB_B, f0);
                mbar_tx_only(f1, 2 * TILEB_B);
                bulk_g2s(dsm + STG_SZ + OFF_BHI, bH + TILEB_B, TILEB_B, f1);
                bulk_g2s(dsm + STG_SZ + OFF_BLO, bL + TILEB_B, TILEB_B, f1);
            }
        }

        // ---------- all threads: wait MMA done, fused epilogue ----------
        mbar_wait(db, (uint32_t)((it - 1) & 1));
        TC_FENCE_AFTER();

        const int sp   = wid & 3;
        const int half = wid >> 2;
        const int lr   = sp * 32 + lane;
        const int r    = bm0 + lr;

#pragma unroll 1
        for (int cb = 0; cb < 128; cb += 32) {
            uint32_t dreg[32];
            LDTM_X32(dreg, tmem + half * 128 + cb);
            TC_WAIT_LD();

            const int coff = half * 128 + cb;
            const int gch  = (bn0 + coff) >> 6;
            const int lc0  = coff & 63;
            const size_t tb = ((size_t)(blockIdx.y * 16 + gch)) * TILEA_B;
            const size_t blin = (size_t)r * Mm + bn0 + coff;

#pragma unroll
            for (int j0 = 0; j0 < 32; j0 += 4) {
                const uint32_t boff = swz((uint32_t)(lr * 128 + (lc0 + j0) * 2));
                float4 cv = *(const float4*)&cc[blin + j0];
                uint64_t h4 = *(const uint64_t*)((const char*)rdH + tb + boff);
                uint64_t l4 = *(const uint64_t*)((const char*)rdL + tb + boff);
                float4 av;
                if (masked) av = *(const float4*)&act[blin + j0];
                const float* cvp = (const float*)&cv;
                const float* avp = (const float*)&av;
                uint16_t oh[4], ol[4];
#pragma unroll
                for (int k = 0; k < 4; k++) {
                    float lamold = bfbits2f((uint16_t)(h4 >> (16 * k)))
                                 + bfbits2f((uint16_t)(l4 >> (16 * k)));
                    float acc = __uint_as_float(dreg[j0 + k]);
                    float v = fmaxf(lamold - STEPC * (acc - cvp[k]), 0.f);
                    if (masked) v *= avp[k];
                    uint16_t hb = f2bfbits(v);
                    oh[k] = hb;
                    ol[k] = f2bfbits(v - bfbits2f(hb));
                }
                *(uint64_t*)((char*)wrH + tb + boff) =
                    (uint64_t)oh[0] | ((uint64_t)oh[1] << 16)
                    | ((uint64_t)oh[2] << 32) | ((uint64_t)oh[3] << 48);
                *(uint64_t*)((char*)wrL + tb + boff) =
                    (uint64_t)ol[0] | ((uint64_t)ol[1] << 16)
                    | ((uint64_t)ol[2] << 32) | ((uint64_t)ol[3] << 48);
            }
        }
        TC_FENCE_BEFORE();

        // ---------- iteration boundary: 4-CTA cluster sync ----------
        if (it < nit) {
            asm volatile("fence.proxy.async;" ::: "memory");
            asm volatile("barrier.cluster.arrive.aligned;" ::: "memory");
            asm volatile("barrier.cluster.wait.aligned;" ::: "memory");
            if (tid == 0) {
                const char* nH = (const char*)wrH + yoffA;
                const char* nL = (const char*)wrL + yoffA;
                mbar_arrive_tx(f0, 2 * TILEA_B);
                bulk_g2s(dsm,                    nH,           TILEA_B, f0);
                bulk_g2s(dsm + OFF_ALO,          nL,           TILEA_B, f0);
                mbar_arrive_tx(f1, 2 * TILEA_B);
                bulk_g2s(dsm + STG_SZ,           nH + TILEA_B, TILEA_B, f1);
                bulk_g2s(dsm + STG_SZ + OFF_ALO, nL + TILEA_B, TILEA_B, f1);
            }
        }
    }

    __syncthreads();
    if (wid == 0) { TC_RELINQ(); TC_DEALLOC(tmem, 256); }
#endif  // HAS_TCGEN05
}

// epilogue variants (cg1 peripheral GEMMs)
enum { E_C = 0, E_ACT, E_MSK, E_Z, E_OUT, E_Q };

// ---------------------------------------------------------------------------
// Generic cg1 tcgen05 GEMM over pre-swizzled tile images, fused epilogues.
// ---------------------------------------------------------------------------
template <int EPI>
__global__ void __launch_bounds__(256, 1) tc_gemm(
    const __nv_bfloat16* __restrict__ Ahi, const __nv_bfloat16* __restrict__ Alo,
    const __nv_bfloat16* __restrict__ Bhi, const __nv_bfloat16* __restrict__ Blo,
    int nch,
    const float* __restrict__ v1, const float* __restrict__ v2,
    float* __restrict__ o32,
    __nv_bfloat16* __restrict__ ohi, __nv_bfloat16* __restrict__ olo,
    int Ncols)
{
#if HAS_TCGEN05
    extern __shared__ char draw[];
    const uint32_t dsm = (s2u(draw) + 1023u) & ~1023u;

    __shared__ uint32_t s_tmem;
    __shared__ __align__(8) uint64_t s_bar[5];

    const int tid  = threadIdx.x;
    const int wid  = tid >> 5;
    const int lane = tid & 31;
    const int bm0  = blockIdx.y * TM;
    const int bn0  = blockIdx.x * TN;

    const uint32_t f0 = s2u(&s_bar[0]);
    const uint32_t f1 = s2u(&s_bar[1]);
    const uint32_t e0 = s2u(&s_bar[2]);
    const uint32_t e1 = s2u(&s_bar[3]);
    const uint32_t db = s2u(&s_bar[4]);

    if (wid == 0) TC_ALLOC(s2u(&s_tmem), 256);
    if (tid == 0) {
        mbar_init(f0, 1); mbar_init(f1, 1);
        mbar_init(e0, 1); mbar_init(e1, 1);
        mbar_init(db, 1);
    }
    __syncthreads();
    uint32_t tmem;
    asm volatile("ld.shared.b32 %0, [%1];" : "=r"(tmem) : "r"(s2u(&s_tmem)));

    if (tid == 0) {
        const char* aH = (const char*)Ahi + (size_t)blockIdx.y * nch * TILEA_B;
        const char* aL = (const char*)Alo + (size_t)blockIdx.y * nch * TILEA_B;
        const char* bH = (const char*)Bhi + (size_t)blockIdx.x * nch * TILEB_B;
        const char* bL = (const char*)Blo + (size_t)blockIdx.x * nch * TILEB_B;

        auto loadch = [&](int ch) {
            const int s = ch & 1;
            const uint32_t fb = s ? f1 : f0;
            const uint32_t st = dsm + (uint32_t)s * STG_SZ;
            mbar_arrive_tx(fb, (uint32_t)STG_SZ);
            bulk_g2s(st,           aH + (size_t)ch * TILEA_B, TILEA_B, fb);
            bulk_g2s(st + OFF_ALO, aL + (size_t)ch * TILEA_B, TILEA_B, fb);
            bulk_g2s(st + OFF_BHI, bH + (size_t)ch * TILEB_B, TILEB_B, fb);
            bulk_g2s(st + OFF_BLO, bL + (size_t)ch * TILEB_B, TILEB_B, fb);
        };
        loadch(0);
        loadch(1);

        uint32_t phf[2] = {0, 0}, phe[2] = {0, 0};
#pragma unroll 1
        for (int ch = 0; ch < nch; ch++) {
            const int s = ch & 1;
            mbar_wait(s ? f1 : f0, phf[s]); phf[s] ^= 1;

            const uint32_t st = dsm + (uint32_t)s * STG_SZ;
            const uint64_t dah = mkdesc(st);
            const uint64_t dal = mkdesc(st + OFF_ALO);
            const uint64_t dbh = mkdesc(st + OFF_BHI);
            const uint64_t dbl = mkdesc(st + OFF_BLO);
#pragma unroll
            for (int ks = 0; ks < 4; ks++) {
                mma_f16_ss(tmem, dah + ks * 2, dbh + ks * 2, GEMM_IDESC,
                           (ch == 0 && ks == 0) ? 0u : 1u);
                mma_f16_ss(tmem, dah + ks * 2, dbl + ks * 2, GEMM_IDESC, 1u);
                mma_f16_ss(tmem, dal + ks * 2, dbh + ks * 2, GEMM_IDESC, 1u);
            }
            tc_commit(s ? e1 : e0);

            if (ch + 2 < nch) {
                mbar_wait(s ? e1 : e0, phe[s]); phe[s] ^= 1;
                loadch(ch + 2);
            }
        }
        tc_commit(db);
    }

    mbar_wait(db, 0);
    TC_FENCE_AFTER();

    const int sp   = wid & 3;
    const int half = wid >> 2;
    const int lr   = sp * 32 + lane;
    const int r    = bm0 + lr;
    const int nchO = Ncols >> 6;

#pragma unroll 1
    for (int cb = 0; cb < 128; cb += 32) {
        uint32_t dreg[32];
        LDTM_X32(dreg, tmem + half * 128 + cb);
        TC_WAIT_LD();

        const int coff = half * 128 + cb;
        const int gch  = (bn0 + coff) >> 6;
        const int lc0  = coff & 63;
        const size_t blin = (size_t)r * Ncols + bn0 + coff;
        const size_t tbA = ((size_t)(blockIdx.y * nchO + gch)) * TILEA_B;
        const size_t tbB = ((size_t)((r >> 8) * nchO + gch)) * TILEB_B;
        const int brow = r & 255;

#pragma unroll
        for (int j0 = 0; j0 < 32; j0 += 4) {
            const uint32_t boffA = swz((uint32_t)(lr * 128 + (lc0 + j0) * 2));
            float res[4];
#pragma unroll
            for (int k = 0; k < 4; k++) res[k] = __uint_as_float(dreg[j0 + k]);

            if (EPI == E_C) {
                float4 bv = *(const float4*)&v1[bn0 + coff + j0];
                const float* bp = (const float*)&bv;
                uint16_t oh[4], ol[4];
                float cvv[4];
#pragma unroll
                for (int k = 0; k < 4; k++) {
                    float cv = res[k] - bp[k];
                    cvv[k] = cv;
                    float v = fmaxf(STEPC * cv, 0.f);
                    uint16_t hb = f2bfbits(v);
                    oh[k] = hb; ol[k] = f2bfbits(v - bfbits2f(hb));
                }
                *(float4*)&o32[blin + j0] = make_float4(cvv[0], cvv[1], cvv[2], cvv[3]);
                *(uint64_t*)((char*)ohi + tbA + boffA) =
                    (uint64_t)oh[0] | ((uint64_t)oh[1] << 16)
                    | ((uint64_t)oh[2] << 32) | ((uint64_t)oh[3] << 48);
                *(uint64_t*)((char*)olo + tbA + boffA) =
                    (uint64_t)ol[0] | ((uint64_t)ol[1] << 16)
                    | ((uint64_t)ol[2] << 32) | ((uint64_t)ol[3] << 48);
            } else if (EPI == E_ACT) {
                float4 bv = *(const float4*)&v1[bn0 + coff + j0];
                const float* bp = (const float*)&bv;
                float o[4];
#pragma unroll
                for (int k = 0; k < 4; k++)
                    o[k] = (res[k] >= bp[k] - TOLV) ? 1.f : 0.f;
                *(float4*)&o32[blin + j0] = make_float4(o[0], o[1], o[2], o[3]);
            } else if (EPI == E_MSK) {
                float4 av = *(const float4*)&v1[blin + j0];
                const float* ap = (const float*)&av;
                uint16_t oh[4], ol[4];
                float mm[4];
#pragma unroll
                for (int k = 0; k < 4; k++) {
                    float m = res[k] * ap[k];
                    mm[k] = m;
                    float v = fmaxf(STEPC * m, 0.f) * ap[k];
                    uint16_t hb = f2bfbits(v);
                    oh[k] = hb; ol[k] = f2bfbits(v - bfbits2f(hb));
                }
                *(float4*)&o32[blin + j0] = make_float4(mm[0], mm[1], mm[2], mm[3]);
                *(uint64_t*)((char*)ohi + tbA + boffA) =
                    (uint64_t)oh[0] | ((uint64_t)oh[1] << 16)
                    | ((uint64_t)oh[2] << 32) | ((uint64_t)oh[3] << 48);
                *(uint64_t*)((char*)olo + tbA + boffA) =
                    (uint64_t)ol[0] | ((uint64_t)ol[1] << 16)
                    | ((uint64_t)ol[2] << 32) | ((uint64_t)ol[3] << 48);
            } else if (EPI == E_Z) {
                float4 xv = *(const float4*)&v1[blin + j0];
                float4 uv = *(const float4*)&v2[blin + j0];
                const float* xp = (const float*)&xv;
                const float* up = (const float*)&uv;
                uint16_t oh[4], ol[4];
#pragma unroll
                for (int k = 0; k < 4; k++) {
                    float zv = xp[k] + up[k] - res[k];
                    uint16_t hb = f2bfbits(zv);
                    oh[k] = hb; ol[k] = f2bfbits(zv - bfbits2f(hb));
                }
                *(uint64_t*)((char*)ohi + tbA + boffA) =
                    (uint64_t)oh[0] | ((uint64_t)oh[1] << 16)
                    | ((uint64_t)oh[2] << 32) | ((uint64_t)oh[3] << 48);
                *(uint64_t*)((char*)olo + tbA + boffA) =
                    (uint64_t)ol[0] | ((uint64_t)ol[1] << 16)
                    | ((uint64_t)ol[2] << 32) | ((uint64_t)ol[3] << 48);
            } else if (EPI == E_OUT) {
                float4 uv = *(const float4*)&v1[blin + j0];
                const float* up = (const float*)&uv;
                float o[4];
#pragma unroll
                for (int k = 0; k < 4; k++) o[k] = up[k] - res[k];
                *(float4*)&o32[blin + j0] = make_float4(o[0], o[1], o[2], o[3]);
            } else if (EPI == E_Q) {
                const uint32_t boffB = swz((uint32_t)(brow * 128 + (lc0 + j0) * 2));
                uint16_t oh[4], ol[4];
#pragma unroll
                for (int k = 0; k < 4; k++) {
                    uint16_t hb = f2bfbits(res[k]);
                    oh[k] = hb; ol[k] = f2bfbits(res[k] - bfbits2f(hb));
                }
                *(uint64_t*)((char*)ohi + tbB + boffB) =
                    (uint64_t)oh[0] | ((uint64_t)oh[1] << 16)
                    | ((uint64_t)oh[2] << 32) | ((uint64_t)oh[3] << 48);
                *(uint64_t*)((char*)olo + tbB + boffB) =
                    (uint64_t)ol[0] | ((uint64_t)ol[1] << 16)
                    | ((uint64_t)ol[2] << 32) | ((uint64_t)ol[3] << 48);
            }
        }
    }

    __syncthreads();
    if (wid == 0) { TC_RELINQ(); TC_DEALLOC(tmem, 256); }
#endif  // HAS_TCGEN05
}

// ---------------- merged prep kernel (one launch) ----------------
__device__ __forceinline__ void img_store(__nv_bfloat16* hi, __nv_bfloat16* lo,
                                          size_t tb, uint32_t boff, float v)
{
    __nv_bfloat16 h = __float2bfloat16(v);
    *(__nv_bfloat16*)((char*)hi + tb + boff) = h;
    *(__nv_bfloat16*)((char*)lo + tb + boff) = __float2bfloat16(v - __bfloat162float(h));
}

__global__ void prep_all(const float* __restrict__ A,
                         const float* __restrict__ x, const float* __restrict__ u)
{
    int i = blockIdx.x * blockDim.x + threadIdx.x;
    // split A into A-image + B-image (i < Mm*Nn)
    if (i < Mm * Nn) {
        int r = i >> 9, k = i & 511;
        float v = A[i];
        int ch = k >> 6, lc = k & 63;
        {
            int bm = r >> 7, lrow = r & 127;
            size_t tb = ((size_t)(bm * 8 + ch)) * TILEA_B;
            img_store(g_AAi_h, g_AAi_l, tb, swz((uint32_t)(lrow * 128 + lc * 2)), v);
        }
        {
            int nb = r >> 8, brow = r & 255;
            size_t tb = ((size_t)(nb * 8 + ch)) * TILEB_B;
            img_store(g_ABi_h, g_ABi_l, tb, swz((uint32_t)(brow * 128 + lc * 2)), v);
        }
        // A^T B-image (same element count, transposed access)
        int n = i >> 10, kk = i & 1023;
        float vt = A[(size_t)kk * Nn + n];
        int nb = n >> 8, brow = n & 255, ch2 = kk >> 6, lc2 = kk & 63;
        size_t tb = ((size_t)(nb * 16 + ch2)) * TILEB_B;
        img_store(g_ATi_h, g_ATi_l, tb, swz((uint32_t)(brow * 128 + lc2 * 2)), vt);
    }
    // split x+u and u (i < Bsz*Nn)
    if (i < Bsz * Nn) {
        int r = i >> 9, k = i & 511;
        int bm = r >> 7, lrow = r & 127, ch = k >> 6, lc = k & 63;
        size_t tb = ((size_t)(bm * 8 + ch)) * TILEA_B;
        uint32_t boff = swz((uint32_t)(lrow * 128 + lc * 2));
        float uv = u[i];
        img_store(g_xu_h, g_xu_l, tb, boff, x[i] + uv);
        img_store(g_u_h,  g_u_l,  tb, boff, uv);
    }
}

// ---------------------------------------------------------------------------
extern "C" void kernel_launch(void* const* d_in, const int* in_sizes, int n_in,
                              void* d_out, int out_size)
{
    const float* x = (const float*)d_in[0];
    const float* u = (const float*)d_in[1];
    const float* A = (const float*)d_in[2];
    const float* b = (const float*)d_in[3];
    float* out = (float*)d_out;

    float *c, *msk, *act;
    __nv_bfloat16 *AAh, *AAl, *ABh, *ABl, *ATh, *ATl, *XUh, *XUl, *Uh, *Ul,
                  *Zh, *Zl, *Qh, *Ql, *lAh, *lAl, *lBh, *lBl;
    cudaGetSymbolAddress((void**)&c,   g_c);
    cudaGetSymbolAddress((void**)&msk, g_msk);
    cudaGetSymbolAddress((void**)&act, g_act);
    cudaGetSymbolAddress((void**)&AAh, g_AAi_h); cudaGetSymbolAddress((void**)&AAl, g_AAi_l);
    cudaGetSymbolAddress((void**)&ABh, g_ABi_h); cudaGetSymbolAddress((void**)&ABl, g_ABi_l);
    cudaGetSymbolAddress((void**)&ATh, g_ATi_h); cudaGetSymbolAddress((void**)&ATl, g_ATi_l);
    cudaGetSymbolAddress((void**)&XUh, g_xu_h);  cudaGetSymbolAddress((void**)&XUl, g_xu_l);
    cudaGetSymbolAddress((void**)&Uh,  g_u_h);   cudaGetSymbolAddress((void**)&Ul,  g_u_l);
    cudaGetSymbolAddress((void**)&Zh,  g_z_h);   cudaGetSymbolAddress((void**)&Zl,  g_z_l);
    cudaGetSymbolAddress((void**)&Qh,  g_Qhi);   cudaGetSymbolAddress((void**)&Ql,  g_Qlo);
    cudaGetSymbolAddress((void**)&lAh, g_lAhi);  cudaGetSymbolAddress((void**)&lAl, g_lAlo);
    cudaGetSymbolAddress((void**)&lBh, g_lBhi);  cudaGetSymbolAddress((void**)&lBl, g_lBlo);

    cudaFuncSetAttribute(tc_gemm<E_C>,   cudaFuncAttributeMaxDynamicSharedMemorySize, DSMEM);
    cudaFuncSetAttribute(tc_gemm<E_ACT>, cudaFuncAttributeMaxDynamicSharedMemorySize, DSMEM);
    cudaFuncSetAttribute(tc_gemm<E_MSK>, cudaFuncAttributeMaxDynamicSharedMemorySize, DSMEM);
    cudaFuncSetAttribute(tc_gemm<E_Z>,   cudaFuncAttributeMaxDynamicSharedMemorySize, DSMEM);
    cudaFuncSetAttribute(tc_gemm<E_OUT>, cudaFuncAttributeMaxDynamicSharedMemorySize, DSMEM);
    cudaFuncSetAttribute(tc_gemm<E_Q>,   cudaFuncAttributeMaxDynamicSharedMemorySize, DSMEM);
    cudaFuncSetAttribute(pgd_cluster,    cudaFuncAttributeMaxDynamicSharedMemorySize, DSMEM);

    const dim3 blk(256);
    const int EW = 256;

    // 0) merged prep
    prep_all<<<(int)(((size_t)Bsz * Nn + EW - 1) / EW), EW>>>(A, x, u);

    // 1) Q = A @ A^T -> Q B-images
    tc_gemm<E_Q><<<dim3(4, 8), blk, DSMEM>>>(AAh, AAl, ABh, ABl, 8,
                                             nullptr, nullptr, nullptr, Qh, Ql, 1024);

    // 2) c = xu @ A^T - b (+ lam init)
    tc_gemm<E_C><<<dim3(4, 32), blk, DSMEM>>>(XUh, XUl, ABh, ABl, 8,
                                              b, nullptr, c, lAh, lAl, 1024);

    // 3) PGD iters 2..50 in ONE clustered launch (49 iterations; final in lB)
    pgd_cluster<<<dim3(4, 32), blk, DSMEM>>>(lAh, lAl, lBh, lBl, Qh, Ql,
                                             c, nullptr, 49, 0);

    // 4) z = x + u - lam @ A
    tc_gemm<E_Z><<<dim3(2, 32), blk, DSMEM>>>(lBh, lBl, ATh, ATl, 16,
                                              x, u, nullptr, Zh, Zl, 512);
    // 5) active
    tc_gemm<E_ACT><<<dim3(4, 32), blk, DSMEM>>>(Zh, Zl, ABh, ABl, 8,
                                                b, nullptr, act, nullptr, nullptr, 1024);
    // 6) masked (+ masked lam init)
    tc_gemm<E_MSK><<<dim3(4, 32), blk, DSMEM>>>(Uh, Ul, ABh, ABl, 8,
                                                act, nullptr, msk, lAh, lAl, 1024);

    // 7) masked PGD iters 2..10 (9 iterations; final in lB)
    pgd_cluster<<<dim3(4, 32), blk, DSMEM>>>(lAh, lAl, lBh, lBl, Qh, Ql,
                                             msk, act, 9, 1);

    // 8) out = u - lam @ A
    tc_gemm<E_OUT><<<dim3(2, 32), blk, DSMEM>>>(lBh, lBl, ATh, ATl, 16,
                                                u, nullptr, out, nullptr, nullptr, 512);
}

// round 11
// speedup vs baseline: 1.8575x; 1.8575x over previous
#include <cuda_runtime.h>
#include <cuda_bf16.h>
#include <cstddef>
#include <cstdint>

// Problem constants (B=4096, n=512, m=1024)
#define Bsz 4096
#define Nn  512
#define Mm  1024
#define STEPC 0.01f
#define TOLV 1e-5f

// ---- tensor tile config ----
#define TM 128
#define TN 256
#define KC 64
#define TILEA_B 16384          // 128x64 bf16 tile bytes
#define TILEB_B 32768          // 256x64 bf16 tile bytes
#define OFF_ALO 16384
#define OFF_BHI 32768
#define OFF_BLO 65536
#define STG_SZ  98304          // 96 KB per stage
#define DSMEM   (2 * STG_SZ + 1024)

#if defined(__CUDA_ARCH__) && defined(__CUDA_ARCH_FEAT_SM103_ALL)
#define HAS_TCGEN05 1
#else
#define HAS_TCGEN05 0
#endif

// ---------------- device scratch (allocation-free) ----------------
__device__ __align__(128) float g_c[(size_t)Bsz * Mm];
__device__ __align__(128) float g_msk[(size_t)Bsz * Mm];
__device__ __align__(128) float g_act[(size_t)Bsz * Mm];
__device__ __align__(128) __nv_bfloat16 g_AAi_h[Mm * Nn];   // A as A-image [8][8]
__device__ __align__(128) __nv_bfloat16 g_AAi_l[Mm * Nn];
__device__ __align__(128) __nv_bfloat16 g_ABi_h[Mm * Nn];   // A as B-image [4][8]
__device__ __align__(128) __nv_bfloat16 g_ABi_l[Mm * Nn];
__device__ __align__(128) __nv_bfloat16 g_ATi_h[Nn * Mm];   // A^T as B-image [2][16]
__device__ __align__(128) __nv_bfloat16 g_ATi_l[Nn * Mm];
__device__ __align__(128) __nv_bfloat16 g_xu_h[(size_t)Bsz * Nn];
__device__ __align__(128) __nv_bfloat16 g_xu_l[(size_t)Bsz * Nn];
__device__ __align__(128) __nv_bfloat16 g_u_h[(size_t)Bsz * Nn];
__device__ __align__(128) __nv_bfloat16 g_u_l[(size_t)Bsz * Nn];
__device__ __align__(128) __nv_bfloat16 g_z_h[(size_t)Bsz * Nn];
__device__ __align__(128) __nv_bfloat16 g_z_l[(size_t)Bsz * Nn];
// Q as B-image [4 nb][16 ch][256x64, 32 KB]
__device__ __align__(128) __nv_bfloat16 g_Qhi[Mm * Mm];
__device__ __align__(128) __nv_bfloat16 g_Qlo[Mm * Mm];
__device__ __align__(128) __nv_bfloat16 g_lAhi[(size_t)Bsz * Mm]; // lam A-images [32][16]
__device__ __align__(128) __nv_bfloat16 g_lAlo[(size_t)Bsz * Mm];
__device__ __align__(128) __nv_bfloat16 g_lBhi[(size_t)Bsz * Mm];
__device__ __align__(128) __nv_bfloat16 g_lBlo[(size_t)Bsz * Mm];

// ---------------- helpers ----------------
__device__ __forceinline__ uint32_t s2u(const void* p) {
    uint32_t a;
    asm("{ .reg .u64 t; cvta.to.shared.u64 t, %1; cvt.u32.u64 %0, t; }"
        : "=r"(a) : "l"(p));
    return a;
}
__device__ __forceinline__ uint32_t swz(uint32_t off) {
    return off ^ ((off >> 3) & 0x70);
}
__device__ __forceinline__ void mbar_init(uint32_t a, uint32_t cnt) {
    asm volatile("mbarrier.init.shared.b64 [%0], %1;" :: "r"(a), "r"(cnt) : "memory");
}
__device__ __forceinline__ void mbar_arrive_tx(uint32_t a, uint32_t bytes) {
    asm volatile("mbarrier.arrive.expect_tx.shared.b64 _, [%0], %1;"
                 :: "r"(a), "r"(bytes) : "memory");
}
__device__ __forceinline__ void mbar_tx_only(uint32_t a, uint32_t bytes) {
    asm volatile("mbarrier.expect_tx.shared.b64 [%0], %1;"
                 :: "r"(a), "r"(bytes) : "memory");
}
__device__ __forceinline__ void mbar_wait(uint32_t a, uint32_t phase) {
    uint32_t done = 0;
    while (!done) {
        asm volatile(
            "{ .reg .pred p; mbarrier.try_wait.parity.shared.b64 p, [%1], %2; "
            "selp.b32 %0, 1, 0, p; }"
            : "=r"(done) : "r"(a), "r"(phase) : "memory");
    }
}
__device__ __forceinline__ void bulk_g2s(uint32_t dst, const void* src,
                                         uint32_t bytes, uint32_t mbar) {
    asm volatile(
        "cp.async.bulk.shared::cluster.global.mbarrier::complete_tx::bytes "
        "[%0], [%1], %2, [%3];"
        :: "r"(dst), "l"(src), "r"(bytes), "r"(mbar) : "memory");
}
__device__ __forceinline__ uint64_t mkdesc(uint32_t addr) {
    return ((uint64_t)2 << 61) | ((uint64_t)1 << 46) | ((uint64_t)64 << 32)
         | ((uint64_t)1 << 16) | ((addr >> 4) & 0x3FFF);
}
#define GEMM_IDESC ((1u<<4) | (1u<<7) | (1u<<10) | ((TN/8)<<17) | ((128/16)<<24))

__device__ __forceinline__ float bfbits2f(uint16_t u) {
    __nv_bfloat16_raw r; r.x = u;
    return __bfloat162float(__nv_bfloat16(r));
}
__device__ __forceinline__ uint16_t f2bfbits(float f) {
    __nv_bfloat16 h = __float2bfloat16(f);
    __nv_bfloat16_raw r = (__nv_bfloat16_raw)h;
    return r.x;
}

#if HAS_TCGEN05
__device__ __forceinline__ void mma_f16_ss(uint32_t d, uint64_t a, uint64_t b,
                                           uint32_t idesc, uint32_t en) {
    asm volatile(
        "{\n\t.reg .pred p;\n\tsetp.ne.u32 p, %5, 0;\n\t"
        "tcgen05.mma.cta_group::1.kind::f16 [%0], %1, %2, %3, {%4,%4,%4,%4}, p;\n\t}"
        :: "r"(d), "l"(a), "l"(b), "r"(idesc), "r"(0u), "r"(en) : "memory");
}
__device__ __forceinline__ void tc_commit(uint32_t mbar) {
    asm volatile(
        "tcgen05.commit.cta_group::1.mbarrier::arrive::one.shared::cluster.b64 [%0];"
        :: "r"(mbar) : "memory");
}
#define TC_ALLOC(sres, n) \
    asm volatile("tcgen05.alloc.cta_group::1.sync.aligned.shared::cta.b32 [%0], %1;" \
                 :: "r"(sres), "r"((uint32_t)(n)) : "memory")
#define TC_RELINQ() \
    asm volatile("tcgen05.relinquish_alloc_permit.cta_group::1.sync.aligned;")
#define TC_DEALLOC(t, n) \
    asm volatile("tcgen05.dealloc.cta_group::1.sync.aligned.b32 %0, %1;" :: "r"(t), "r"((uint32_t)(n)))
#define TC_FENCE_AFTER()  asm volatile("tcgen05.fence::after_thread_sync;" ::: "memory")
#define TC_WAIT_LD()      asm volatile("tcgen05.wait::ld.sync.aligned;" ::: "memory")
#define LDTM_X32(r, a) \
    asm volatile( \
        "tcgen05.ld.sync.aligned.32x32b.x32.b32 " \
        "{%0,%1,%2,%3,%4,%5,%6,%7,%8,%9,%10,%11,%12,%13,%14,%15," \
        "%16,%17,%18,%19,%20,%21,%22,%23,%24,%25,%26,%27,%28,%29,%30,%31}, [%32];" \
        : "=r"((r)[0]),"=r"((r)[1]),"=r"((r)[2]),"=r"((r)[3]), \
          "=r"((r)[4]),"=r"((r)[5]),"=r"((r)[6]),"=r"((r)[7]), \
          "=r"((r)[8]),"=r"((r)[9]),"=r"((r)[10]),"=r"((r)[11]), \
          "=r"((r)[12]),"=r"((r)[13]),"=r"((r)[14]),"=r"((r)[15]), \
          "=r"((r)[16]),"=r"((r)[17]),"=r"((r)[18]),"=r"((r)[19]), \
          "=r"((r)[20]),"=r"((r)[21]),"=r"((r)[22]),"=r"((r)[23]), \
          "=r"((r)[24]),"=r"((r)[25]),"=r"((r)[26]),"=r"((r)[27]), \
          "=r"((r)[28]),"=r"((r)[29]),"=r"((r)[30]),"=r"((r)[31]) \
        : "r"(a))
#endif  // HAS_TCGEN05

// ---------------------------------------------------------------------------
// PGD iteration with Programmatic Dependent Launch:
//   - Q (B operand) chunks 0,1 issued BEFORE griddepcontrol.wait (iteration-
//     invariant, safe vs predecessor's in-flight lam writes)
//   - all threads griddepcontrol.wait, then tid0 issues lam (A) loads
//   - epilogue: LDTM issued, GMEM operands gathered, THEN wait on TMEM
//   - after stores: griddepcontrol.launch_dependents
// ---------------------------------------------------------------------------
__global__ void __launch_bounds__(256, 1) pgd_pdl(
    const __nv_bfloat16* __restrict__ Ahi, const __nv_bfloat16* __restrict__ Alo,
    const __nv_bfloat16* __restrict__ Bhi, const __nv_bfloat16* __restrict__ Blo,
    const float* __restrict__ cc, const float* __restrict__ act,
    __nv_bfloat16* __restrict__ ohi, __nv_bfloat16* __restrict__ olo,
    int masked)
{
#if HAS_TCGEN05
    extern __shared__ char draw[];
    const uint32_t dsm = (s2u(draw) + 1023u) & ~1023u;

    __shared__ uint32_t s_tmem;
    __shared__ __align__(8) uint64_t s_bar[5];

    const int tid  = threadIdx.x;
    const int wid  = tid >> 5;
    const int lane = tid & 31;
    const int bm0  = blockIdx.y * TM;
    const int bn0  = blockIdx.x * TN;

    const uint32_t f0 = s2u(&s_bar[0]);
    const uint32_t f1 = s2u(&s_bar[1]);
    const uint32_t e0 = s2u(&s_bar[2]);
    const uint32_t e1 = s2u(&s_bar[3]);
    const uint32_t db = s2u(&s_bar[4]);

    if (wid == 0) TC_ALLOC(s2u(&s_tmem), 256);
    if (tid == 0) {
        mbar_init(f0, 1); mbar_init(f1, 1);
        mbar_init(e0, 1); mbar_init(e1, 1);
        mbar_init(db, 1);
    }
    __syncthreads();
    uint32_t tmem;
    asm volatile("ld.shared.b32 %0, [%1];" : "=r"(tmem) : "r"(s2u(&s_tmem)));

    const char* aH = (const char*)Ahi + (size_t)blockIdx.y * 16 * TILEA_B;
    const char* aL = (const char*)Alo + (size_t)blockIdx.y * 16 * TILEA_B;
    const char* bH = (const char*)Bhi + (size_t)blockIdx.x * 16 * TILEB_B;
    const char* bL = (const char*)Blo + (size_t)blockIdx.x * 16 * TILEB_B;

    // early Q loads for stages 0,1 (tx only — arrival comes with A loads)
    if (tid == 0) {
#pragma unroll
        for (int ch = 0; ch < 2; ch++) {
            const uint32_t fb = ch ? f1 : f0;
            const uint32_t st = dsm + (uint32_t)ch * STG_SZ;
            mbar_tx_only(fb, 2 * TILEB_B);
            bulk_g2s(st + OFF_BHI, bH + (size_t)ch * TILEB_B, TILEB_B, fb);
            bulk_g2s(st + OFF_BLO, bL + (size_t)ch * TILEB_B, TILEB_B, fb);
        }
    }

    // wait for predecessor's writes (lam, c/msk/act) to become visible
    asm volatile("griddepcontrol.wait;" ::: "memory");

    if (tid == 0) {
#pragma unroll
        for (int ch = 0; ch < 2; ch++) {
            const uint32_t fb = ch ? f1 : f0;
            const uint32_t st = dsm + (uint32_t)ch * STG_SZ;
            mbar_arrive_tx(fb, 2 * TILEA_B);
            bulk_g2s(st,           aH + (size_t)ch * TILEA_B, TILEA_B, fb);
            bulk_g2s(st + OFF_ALO, aL + (size_t)ch * TILEA_B, TILEA_B, fb);
        }

        uint32_t phf[2] = {0, 0}, phe[2] = {0, 0};
#pragma unroll 1
        for (int ch = 0; ch < 16; ch++) {
            const int s = ch & 1;
            mbar_wait(s ? f1 : f0, phf[s]); phf[s] ^= 1;

            const uint32_t st = dsm + (uint32_t)s * STG_SZ;
            const uint64_t dah = mkdesc(st);
            const uint64_t dal = mkdesc(st + OFF_ALO);
            const uint64_t dbh = mkdesc(st + OFF_BHI);
            const uint64_t dbl = mkdesc(st + OFF_BLO);
#pragma unroll
            for (int ks = 0; ks < 4; ks++) {
                mma_f16_ss(tmem, dah + ks * 2, dbh + ks * 2, GEMM_IDESC,
                           (ch == 0 && ks == 0) ? 0u : 1u);
                mma_f16_ss(tmem, dah + ks * 2, dbl + ks * 2, GEMM_IDESC, 1u);
                mma_f16_ss(tmem, dal + ks * 2, dbh + ks * 2, GEMM_IDESC, 1u);
            }
            tc_commit(s ? e1 : e0);

            if (ch + 2 < 16) {
                mbar_wait(s ? e1 : e0, phe[s]); phe[s] ^= 1;
                const int nx = ch + 2;
                const uint32_t fb = s ? f1 : f0;
                const uint32_t st2 = dsm + (uint32_t)s * STG_SZ;
                mbar_arrive_tx(fb, (uint32_t)STG_SZ);
                bulk_g2s(st2,           aH + (size_t)nx * TILEA_B, TILEA_B, fb);
                bulk_g2s(st2 + OFF_ALO, aL + (size_t)nx * TILEA_B, TILEA_B, fb);
                bulk_g2s(st2 + OFF_BHI, bH + (size_t)nx * TILEB_B, TILEB_B, fb);
                bulk_g2s(st2 + OFF_BLO, bL + (size_t)nx * TILEB_B, TILEB_B, fb);
            }
        }
        tc_commit(db);
    }

    mbar_wait(db, 0);
    TC_FENCE_AFTER();

    // ---------------- fused epilogue (operands gathered before TMEM wait) ----
    const int sp   = wid & 3;
    const int half = wid >> 2;
    const int lr   = sp * 32 + lane;
    const int r    = bm0 + lr;

#pragma unroll 1
    for (int cb = 0; cb < 128; cb += 32) {
        uint32_t dreg[32];
        LDTM_X32(dreg, tmem + half * 128 + cb);

        const int coff = half * 128 + cb;
        const int gch  = (bn0 + coff) >> 6;
        const int lc0  = coff & 63;
        const size_t tb = ((size_t)(blockIdx.y * 16 + gch)) * TILEA_B;
        const size_t blin = (size_t)r * Mm + bn0 + coff;

        float4   cv[8];
        uint64_t h4[8], l4[8];
        float4   av[8];
        uint32_t boff[8];
#pragma unroll
        for (int g = 0; g < 8; g++) {
            const int j0 = g * 4;
            boff[g] = swz((uint32_t)(lr * 128 + (lc0 + j0) * 2));
            cv[g] = *(const float4*)&cc[blin + j0];
            h4[g] = *(const uint64_t*)((const char*)Ahi + tb + boff[g]);
            l4[g] = *(const uint64_t*)((const char*)Alo + tb + boff[g]);
            if (masked) av[g] = *(const float4*)&act[blin + j0];
        }

        TC_WAIT_LD();

#pragma unroll
        for (int g = 0; g < 8; g++) {
            const int j0 = g * 4;
            const float* cvp = (const float*)&cv[g];
            const float* avp = (const float*)&av[g];
            uint16_t oh[4], ol[4];
#pragma unroll
            for (int k = 0; k < 4; k++) {
                float lamold = bfbits2f((uint16_t)(h4[g] >> (16 * k)))
                             + bfbits2f((uint16_t)(l4[g] >> (16 * k)));
                float acc = __uint_as_float(dreg[j0 + k]);
                float v = fmaxf(lamold - STEPC * (acc - cvp[k]), 0.f);
                if (masked) v *= avp[k];
                uint16_t hb = f2bfbits(v);
                oh[k] = hb;
                ol[k] = f2bfbits(v - bfbits2f(hb));
            }
            *(uint64_t*)((char*)ohi + tb + boff[g]) =
                (uint64_t)oh[0] | ((uint64_t)oh[1] << 16)
                | ((uint64_t)oh[2] << 32) | ((uint64_t)oh[3] << 48);
            *(uint64_t*)((char*)olo + tb + boff[g]) =
                (uint64_t)ol[0] | ((uint64_t)ol[1] << 16)
                | ((uint64_t)ol[2] << 32) | ((uint64_t)ol[3] << 48);
        }
    }

    // signal: dependents may launch (our lam writes are done)
    asm volatile("griddepcontrol.launch_dependents;" ::: "memory");

    __syncthreads();
    if (wid == 0) { TC_RELINQ(); TC_DEALLOC(tmem, 256); }
#endif  // HAS_TCGEN05
}

// epilogue variants (cg1 peripheral GEMMs)
enum { E_C = 0, E_ACT, E_MSK, E_Z, E_OUT, E_Q };

// ---------------------------------------------------------------------------
// Generic cg1 tcgen05 GEMM over pre-swizzled tile images, fused epilogues.
// ---------------------------------------------------------------------------
template <int EPI>
__global__ void __launch_bounds__(256, 1) tc_gemm(
    const __nv_bfloat16* __restrict__ Ahi, const __nv_bfloat16* __restrict__ Alo,
    const __nv_bfloat16* __restrict__ Bhi, const __nv_bfloat16* __restrict__ Blo,
    int nch,
    const float* __restrict__ v1, const float* __restrict__ v2,
    float* __restrict__ o32,
    __nv_bfloat16* __restrict__ ohi, __nv_bfloat16* __restrict__ olo,
    int Ncols)
{
#if HAS_TCGEN05
    extern __shared__ char draw[];
    const uint32_t dsm = (s2u(draw) + 1023u) & ~1023u;

    __shared__ uint32_t s_tmem;
    __shared__ __align__(8) uint64_t s_bar[5];

    const int tid  = threadIdx.x;
    const int wid  = tid >> 5;
    const int lane = tid & 31;
    const int bm0  = blockIdx.y * TM;
    const int bn0  = blockIdx.x * TN;

    const uint32_t f0 = s2u(&s_bar[0]);
    const uint32_t f1 = s2u(&s_bar[1]);
    const uint32_t e0 = s2u(&s_bar[2]);
    const uint32_t e1 = s2u(&s_bar[3]);
    const uint32_t db = s2u(&s_bar[4]);

    if (wid == 0) TC_ALLOC(s2u(&s_tmem), 256);
    if (tid == 0) {
        mbar_init(f0, 1); mbar_init(f1, 1);
        mbar_init(e0, 1); mbar_init(e1, 1);
        mbar_init(db, 1);
    }
    __syncthreads();
    uint32_t tmem;
    asm volatile("ld.shared.b32 %0, [%1];" : "=r"(tmem) : "r"(s2u(&s_tmem)));

    if (tid == 0) {
        const char* aH = (const char*)Ahi + (size_t)blockIdx.y * nch * TILEA_B;
        const char* aL = (const char*)Alo + (size_t)blockIdx.y * nch * TILEA_B;
        const char* bH = (const char*)Bhi + (size_t)blockIdx.x * nch * TILEB_B;
        const char* bL = (const char*)Blo + (size_t)blockIdx.x * nch * TILEB_B;

        auto loadch = [&](int ch) {
            const int s = ch & 1;
            const uint32_t fb = s ? f1 : f0;
            const uint32_t st = dsm + (uint32_t)s * STG_SZ;
            mbar_arrive_tx(fb, (uint32_t)STG_SZ);
            bulk_g2s(st,           aH + (size_t)ch * TILEA_B, TILEA_B, fb);
            bulk_g2s(st + OFF_ALO, aL + (size_t)ch * TILEA_B, TILEA_B, fb);
            bulk_g2s(st + OFF_BHI, bH + (size_t)ch * TILEB_B, TILEB_B, fb);
            bulk_g2s(st + OFF_BLO, bL + (size_t)ch * TILEB_B, TILEB_B, fb);
        };
        loadch(0);
        loadch(1);

        uint32_t phf[2] = {0, 0}, phe[2] = {0, 0};
#pragma unroll 1
        for (int ch = 0; ch < nch; ch++) {
            const int s = ch & 1;
            mbar_wait(s ? f1 : f0, phf[s]); phf[s] ^= 1;

            const uint32_t st = dsm + (uint32_t)s * STG_SZ;
            const uint64_t dah = mkdesc(st);
            const uint64_t dal = mkdesc(st + OFF_ALO);
            const uint64_t dbh = mkdesc(st + OFF_BHI);
            const uint64_t dbl = mkdesc(st + OFF_BLO);
#pragma unroll
            for (int ks = 0; ks < 4; ks++) {
                mma_f16_ss(tmem, dah + ks * 2, dbh + ks * 2, GEMM_IDESC,
                           (ch == 0 && ks == 0) ? 0u : 1u);
                mma_f16_ss(tmem, dah + ks * 2, dbl + ks * 2, GEMM_IDESC, 1u);
                mma_f16_ss(tmem, dal + ks * 2, dbh + ks * 2, GEMM_IDESC, 1u);
            }
            tc_commit(s ? e1 : e0);

            if (ch + 2 < nch) {
                mbar_wait(s ? e1 : e0, phe[s]); phe[s] ^= 1;
                loadch(ch + 2);
            }
        }
        tc_commit(db);
    }

    mbar_wait(db, 0);
    TC_FENCE_AFTER();

    const int sp   = wid & 3;
    const int half = wid >> 2;
    const int lr   = sp * 32 + lane;
    const int r    = bm0 + lr;
    const int nchO = Ncols >> 6;

#pragma unroll 1
    for (int cb = 0; cb < 128; cb += 32) {
        uint32_t dreg[32];
        LDTM_X32(dreg, tmem + half * 128 + cb);
        TC_WAIT_LD();

        const int coff = half * 128 + cb;
        const int gch  = (bn0 + coff) >> 6;
        const int lc0  = coff & 63;
        const size_t blin = (size_t)r * Ncols + bn0 + coff;
        const size_t tbA = ((size_t)(blockIdx.y * nchO + gch)) * TILEA_B;
        const size_t tbB = ((size_t)((r >> 8) * nchO + gch)) * TILEB_B;
        const int brow = r & 255;

#pragma unroll
        for (int j0 = 0; j0 < 32; j0 += 4) {
            const uint32_t boffA = swz((uint32_t)(lr * 128 + (lc0 + j0) * 2));
            float res[4];
#pragma unroll
            for (int k = 0; k < 4; k++) res[k] = __uint_as_float(dreg[j0 + k]);

            if (EPI == E_C) {
                float4 bv = *(const float4*)&v1[bn0 + coff + j0];
                const float* bp = (const float*)&bv;
                uint16_t oh[4], ol[4];
                float cvv[4];
#pragma unroll
                for (int k = 0; k < 4; k++) {
                    float cv = res[k] - bp[k];
                    cvv[k] = cv;
                    float v = fmaxf(STEPC * cv, 0.f);
                    uint16_t hb = f2bfbits(v);
                    oh[k] = hb; ol[k] = f2bfbits(v - bfbits2f(hb));
                }
                *(float4*)&o32[blin + j0] = make_float4(cvv[0], cvv[1], cvv[2], cvv[3]);
                *(uint64_t*)((char*)ohi + tbA + boffA) =
                    (uint64_t)oh[0] | ((uint64_t)oh[1] << 16)
                    | ((uint64_t)oh[2] << 32) | ((uint64_t)oh[3] << 48);
                *(uint64_t*)((char*)olo + tbA + boffA) =
                    (uint64_t)ol[0] | ((uint64_t)ol[1] << 16)
                    | ((uint64_t)ol[2] << 32) | ((uint64_t)ol[3] << 48);
            } else if (EPI == E_ACT) {
                float4 bv = *(const float4*)&v1[bn0 + coff + j0];
                const float* bp = (const float*)&bv;
                float o[4];
#pragma unroll
                for (int k = 0; k < 4; k++)
                    o[k] = (res[k] >= bp[k] - TOLV) ? 1.f : 0.f;
                *(float4*)&o32[blin + j0] = make_float4(o[0], o[1], o[2], o[3]);
            } else if (EPI == E_MSK) {
                float4 avv = *(const float4*)&v1[blin + j0];
                const float* ap = (const float*)&avv;
                uint16_t oh[4], ol[4];
                float mm[4];
#pragma unroll
                for (int k = 0; k < 4; k++) {
                    float m = res[k] * ap[k];
                    mm[k] = m;
                    float v = fmaxf(STEPC * m, 0.f) * ap[k];
                    uint16_t hb = f2bfbits(v);
                    oh[k] = hb; ol[k] = f2bfbits(v - bfbits2f(hb));
                }
                *(float4*)&o32[blin + j0] = make_float4(mm[0], mm[1], mm[2], mm[3]);
                *(uint64_t*)((char*)ohi + tbA + boffA) =
                    (uint64_t)oh[0] | ((uint64_t)oh[1] << 16)
                    | ((uint64_t)oh[2] << 32) | ((uint64_t)oh[3] << 48);
                *(uint64_t*)((char*)olo + tbA + boffA) =
                    (uint64_t)ol[0] | ((uint64_t)ol[1] << 16)
                    | ((uint64_t)ol[2] << 32) | ((uint64_t)ol[3] << 48);
            } else if (EPI == E_Z) {
                float4 xv = *(const float4*)&v1[blin + j0];
                float4 uv = *(const float4*)&v2[blin + j0];
                const float* xp = (const float*)&xv;
                const float* up = (const float*)&uv;
                uint16_t oh[4], ol[4];
#pragma unroll
                for (int k = 0; k < 4; k++) {
                    float zv = xp[k] + up[k] - res[k];
                    uint16_t hb = f2bfbits(zv);
                    oh[k] = hb; ol[k] = f2bfbits(zv - bfbits2f(hb));
                }
                *(uint64_t*)((char*)ohi + tbA + boffA) =
                    (uint64_t)oh[0] | ((uint64_t)oh[1] << 16)
                    | ((uint64_t)oh[2] << 32) | ((uint64_t)oh[3] << 48);
                *(uint64_t*)((char*)olo + tbA + boffA) =
                    (uint64_t)ol[0] | ((uint64_t)ol[1] << 16)
                    | ((uint64_t)ol[2] << 32) | ((uint64_t)ol[3] << 48);
            } else if (EPI == E_OUT) {
                float4 uv = *(const float4*)&v1[blin + j0];
                const float* up = (const float*)&uv;
                float o[4];
#pragma unroll
                for (int k = 0; k < 4; k++) o[k] = up[k] - res[k];
                *(float4*)&o32[blin + j0] = make_float4(o[0], o[1], o[2], o[3]);
            } else if (EPI == E_Q) {
                const uint32_t boffB = swz((uint32_t)(brow * 128 + (lc0 + j0) * 2));
                uint16_t oh[4], ol[4];
#pragma unroll
                for (int k = 0; k < 4; k++) {
                    uint16_t hb = f2bfbits(res[k]);
                    oh[k] = hb; ol[k] = f2bfbits(res[k] - bfbits2f(hb));
                }
                *(uint64_t*)((char*)ohi + tbB + boffB) =
                    (uint64_t)oh[0] | ((uint64_t)oh[1] << 16)
                    | ((uint64_t)oh[2] << 32) | ((uint64_t)oh[3] << 48);
                *(uint64_t*)((char*)olo + tbB + boffB) =
                    (uint64_t)ol[0] | ((uint64_t)ol[1] << 16)
                    | ((uint64_t)ol[2] << 32) | ((uint64_t)ol[3] << 48);
            }
        }
    }

    __syncthreads();
    if (wid == 0) { TC_RELINQ(); TC_DEALLOC(tmem, 256); }
#endif  // HAS_TCGEN05
}

// ---------------- prep kernels (one-time splits into tile images) ----------------
__device__ __forceinline__ void img_store(__nv_bfloat16* hi, __nv_bfloat16* lo,
                                          size_t tb, uint32_t boff, float v)
{
    __nv_bfloat16 h = __float2bfloat16(v);
    *(__nv_bfloat16*)((char*)hi + tb + boff) = h;
    *(__nv_bfloat16*)((char*)lo + tb + boff) = __float2bfloat16(v - __bfloat162float(h));
}

__global__ void split_A_images(const float* __restrict__ A)
{
    int i = blockIdx.x * blockDim.x + threadIdx.x;
    if (i >= Mm * Nn) return;
    int r = i >> 9, k = i & 511;
    float v = A[i];
    int ch = k >> 6, lc = k & 63;
    {
        int bm = r >> 7, lrow = r & 127;
        size_t tb = ((size_t)(bm * 8 + ch)) * TILEA_B;
        img_store(g_AAi_h, g_AAi_l, tb, swz((uint32_t)(lrow * 128 + lc * 2)), v);
    }
    {
        int nb = r >> 8, brow = r & 255;
        size_t tb = ((size_t)(nb * 8 + ch)) * TILEB_B;
        img_store(g_ABi_h, g_ABi_l, tb, swz((uint32_t)(brow * 128 + lc * 2)), v);
    }
}

__global__ void split_AT_image(const float* __restrict__ A)
{
    int i = blockIdx.x * blockDim.x + threadIdx.x;
    if (i >= Nn * Mm) return;
    int n = i >> 10, k = i & 1023;
    float v = A[(size_t)k * Nn + n];
    int nb = n >> 8, brow = n & 255, ch = k >> 6, lc = k & 63;
    size_t tb = ((size_t)(nb * 16 + ch)) * TILEB_B;
    img_store(g_ATi_h, g_ATi_l, tb, swz((uint32_t)(brow * 128 + lc * 2)), v);
}

__global__ void split_xu_u(const float* __restrict__ x, const float* __restrict__ u)
{
    int i = blockIdx.x * blockDim.x + threadIdx.x;
    if (i >= Bsz * Nn) return;
    int r = i >> 9, k = i & 511;
    int bm = r >> 7, lrow = r & 127, ch = k >> 6, lc = k & 63;
    size_t tb = ((size_t)(bm * 8 + ch)) * TILEA_B;
    uint32_t boff = swz((uint32_t)(lrow * 128 + lc * 2));
    float uv = u[i];
    img_store(g_xu_h, g_xu_l, tb, boff, x[i] + uv);
    img_store(g_u_h,  g_u_l,  tb, boff, uv);
}

// ---------------------------------------------------------------------------
extern "C" void kernel_launch(void* const* d_in, const int* in_sizes, int n_in,
                              void* d_out, int out_size)
{
    const float* x = (const float*)d_in[0];
    const float* u = (const float*)d_in[1];
    const float* A = (const float*)d_in[2];
    const float* b = (const float*)d_in[3];
    float* out = (float*)d_out;

    float *c, *msk, *act;
    __nv_bfloat16 *AAh, *AAl, *ABh, *ABl, *ATh, *ATl, *XUh, *XUl, *Uh, *Ul,
                  *Zh, *Zl, *Qh, *Ql, *lAh, *lAl, *lBh, *lBl;
    cudaGetSymbolAddress((void**)&c,   g_c);
    cudaGetSymbolAddress((void**)&msk, g_msk);
    cudaGetSymbolAddress((void**)&act, g_act);
    cudaGetSymbolAddress((void**)&AAh, g_AAi_h); cudaGetSymbolAddress((void**)&AAl, g_AAi_l);
    cudaGetSymbolAddress((void**)&ABh, g_ABi_h); cudaGetSymbolAddress((void**)&ABl, g_ABi_l);
    cudaGetSymbolAddress((void**)&ATh, g_ATi_h); cudaGetSymbolAddress((void**)&ATl, g_ATi_l);
    cudaGetSymbolAddress((void**)&XUh, g_xu_h);  cudaGetSymbolAddress((void**)&XUl, g_xu_l);
    cudaGetSymbolAddress((void**)&Uh,  g_u_h);   cudaGetSymbolAddress((void**)&Ul,  g_u_l);
    cudaGetSymbolAddress((void**)&Zh,  g_z_h);   cudaGetSymbolAddress((void**)&Zl,  g_z_l);
    cudaGetSymbolAddress((void**)&Qh,  g_Qhi);   cudaGetSymbolAddress((void**)&Ql,  g_Qlo);
    cudaGetSymbolAddress((void**)&lAh, g_lAhi);  cudaGetSymbolAddress((void**)&lAl, g_lAlo);
    cudaGetSymbolAddress((void**)&lBh, g_lBhi);  cudaGetSymbolAddress((void**)&lBl, g_lBlo);

    cudaFuncSetAttribute(tc_gemm<E_C>,   cudaFuncAttributeMaxDynamicSharedMemorySize, DSMEM);
    cudaFuncSetAttribute(tc_gemm<E_ACT>, cudaFuncAttributeMaxDynamicSharedMemorySize, DSMEM);
    cudaFuncSetAttribute(tc_gemm<E_MSK>, cudaFuncAttributeMaxDynamicSharedMemorySize, DSMEM);
    cudaFuncSetAttribute(tc_gemm<E_Z>,   cudaFuncAttributeMaxDynamicSharedMemorySize, DSMEM);
    cudaFuncSetAttribute(tc_gemm<E_OUT>, cudaFuncAttributeMaxDynamicSharedMemorySize, DSMEM);
    cudaFuncSetAttribute(tc_gemm<E_Q>,   cudaFuncAttributeMaxDynamicSharedMemorySize, DSMEM);
    cudaFuncSetAttribute(pgd_pdl,        cudaFuncAttributeMaxDynamicSharedMemorySize, DSMEM);

    const dim3 blk(256);
    const int EW = 256;

    // prep
    split_A_images<<<(Mm * Nn + EW - 1) / EW, EW>>>(A);
    split_AT_image<<<(Nn * Mm + EW - 1) / EW, EW>>>(A);
    split_xu_u<<<(int)(((size_t)Bsz * Nn + EW - 1) / EW), EW>>>(x, u);

    // Q = A @ A^T -> Q B-images
    tc_gemm<E_Q><<<dim3(4, 8), blk, DSMEM>>>(AAh, AAl, ABh, ABl, 8,
                                             nullptr, nullptr, nullptr, Qh, Ql, 1024);

    // c = xu @ A^T - b (+ lam init)
    tc_gemm<E_C><<<dim3(4, 32), blk, DSMEM>>>(XUh, XUl, ABh, ABl, 8,
                                              b, nullptr, c, lAh, lAl, 1024);

    // PDL launch config for the PGD chain
    cudaLaunchAttribute pdlAttr;
    pdlAttr.id = cudaLaunchAttributeProgrammaticStreamSerialization;
    pdlAttr.val.programmaticStreamSerializationAllowed = 1;
    cudaLaunchConfig_t cfg = {};
    cfg.gridDim = dim3(4, 32);
    cfg.blockDim = blk;
    cfg.dynamicSmemBytes = DSMEM;
    cfg.stream = 0;
    cfg.attrs = &pdlAttr;
    cfg.numAttrs = 1;

    // PGD iters 2..50 (49 PDL launches)
    __nv_bfloat16 *curh = lAh, *curl = lAl, *nxth = lBh, *nxtl = lBl;
    for (int it = 1; it < 50; it++) {
        cudaLaunchKernelEx(&cfg, pgd_pdl,
                           (const __nv_bfloat16*)curh, (const __nv_bfloat16*)curl,
                           (const __nv_bfloat16*)Qh,  (const __nv_bfloat16*)Ql,
                           (const float*)c, (const float*)nullptr,
                           nxth, nxtl, 0);
        __nv_bfloat16* t;
        t = curh; curh = nxth; nxth = t;
        t = curl; curl = nxtl; nxtl = t;
    }

    // z = x + u - lam @ A
    tc_gemm<E_Z><<<dim3(2, 32), blk, DSMEM>>>(curh, curl, ATh, ATl, 16,
                                              x, u, nullptr, Zh, Zl, 512);
    // active
    tc_gemm<E_ACT><<<dim3(4, 32), blk, DSMEM>>>(Zh, Zl, ABh, ABl, 8,
                                                b, nullptr, act, nullptr, nullptr, 1024);
    // masked (+ masked lam init)
    tc_gemm<E_MSK><<<dim3(4, 32), blk, DSMEM>>>(Uh, Ul, ABh, ABl, 8,
                                                act, nullptr, msk, lAh, lAl, 1024);

    // masked PGD iters 2..10 (9 PDL launches)
    curh = lAh; curl = lAl; nxth = lBh; nxtl = lBl;
    for (int it = 1; it < 10; it++) {
        cudaLaunchKernelEx(&cfg, pgd_pdl,
                           (const __nv_bfloat16*)curh, (const __nv_bfloat16*)curl,
                           (const __nv_bfloat16*)Qh,  (const __nv_bfloat16*)Ql,
                           (const float*)msk, (const float*)act,
                           nxth, nxtl, 1);
        __nv_bfloat16* t;
        t = curh; curh = nxth; nxth = t;
        t = curl; curl = nxtl; nxtl = t;
    }

    // out = u - lam @ A
    tc_gemm<E_OUT><<<dim3(2, 32), blk, DSMEM>>>(curh, curl, ATh, ATl, 16,
                                                u, nullptr, out, nullptr, nullptr, 512);
}

// round 12
// speedup vs baseline: 2.0726x; 1.1158x over previous
#include <cuda_runtime.h>
#include <cuda_bf16.h>
#include <cstddef>
#include <cstdint>

// Problem constants (B=4096, n=512, m=1024)
#define Bsz 4096
#define Nn  512
#define Mm  1024
#define STEPC 0.01f
#define TOLV 1e-5f

// ---- tensor tile config ----
#define TM 128
#define TN 256
#define KC 64
#define TILEA_B 16384          // 128x64 bf16 tile bytes
#define TILEB_B 32768          // 256x64 bf16 tile bytes
#define OFF_ALO 16384
#define OFF_BHI 32768
#define OFF_BLO 65536
#define STG_SZ  98304          // 96 KB per stage
#define DSMEM   (2 * STG_SZ + 1024)

#if defined(__CUDA_ARCH__) && defined(__CUDA_ARCH_FEAT_SM103_ALL)
#define HAS_TCGEN05 1
#else
#define HAS_TCGEN05 0
#endif

// ---------------- device scratch (allocation-free) ----------------
__device__ __align__(128) float g_c[(size_t)Bsz * Mm];
__device__ __align__(128) float g_msk[(size_t)Bsz * Mm];
__device__ __align__(128) float g_act[(size_t)Bsz * Mm];
__device__ __align__(128) __nv_bfloat16 g_AAi_h[Mm * Nn];   // A as A-image [8][8]
__device__ __align__(128) __nv_bfloat16 g_AAi_l[Mm * Nn];
__device__ __align__(128) __nv_bfloat16 g_ABi_h[Mm * Nn];   // A as B-image [4][8]
__device__ __align__(128) __nv_bfloat16 g_ABi_l[Mm * Nn];
__device__ __align__(128) __nv_bfloat16 g_ATi_h[Nn * Mm];   // A^T as B-image [2][16]
__device__ __align__(128) __nv_bfloat16 g_ATi_l[Nn * Mm];
__device__ __align__(128) __nv_bfloat16 g_xu_h[(size_t)Bsz * Nn];
__device__ __align__(128) __nv_bfloat16 g_xu_l[(size_t)Bsz * Nn];
__device__ __align__(128) __nv_bfloat16 g_u_h[(size_t)Bsz * Nn];
__device__ __align__(128) __nv_bfloat16 g_u_l[(size_t)Bsz * Nn];
__device__ __align__(128) __nv_bfloat16 g_z_h[(size_t)Bsz * Nn];
__device__ __align__(128) __nv_bfloat16 g_z_l[(size_t)Bsz * Nn];
// Q as B-image [4 nb][16 ch][256x64, 32 KB]
__device__ __align__(128) __nv_bfloat16 g_Qhi[Mm * Mm];
__device__ __align__(128) __nv_bfloat16 g_Qlo[Mm * Mm];
__device__ __align__(128) __nv_bfloat16 g_lAhi[(size_t)Bsz * Mm]; // lam A-images [32][16]
__device__ __align__(128) __nv_bfloat16 g_lAlo[(size_t)Bsz * Mm];
__device__ __align__(128) __nv_bfloat16 g_lBhi[(size_t)Bsz * Mm];
__device__ __align__(128) __nv_bfloat16 g_lBlo[(size_t)Bsz * Mm];

// ---------------- helpers ----------------
__device__ __forceinline__ uint32_t s2u(const void* p) {
    uint32_t a;
    asm("{ .reg .u64 t; cvta.to.shared.u64 t, %1; cvt.u32.u64 %0, t; }"
        : "=r"(a) : "l"(p));
    return a;
}
__device__ __forceinline__ uint32_t swz(uint32_t off) {
    return off ^ ((off >> 3) & 0x70);
}
__device__ __forceinline__ void mbar_init(uint32_t a, uint32_t cnt) {
    asm volatile("mbarrier.init.shared.b64 [%0], %1;" :: "r"(a), "r"(cnt) : "memory");
}
__device__ __forceinline__ void mbar_arrive_tx(uint32_t a, uint32_t bytes) {
    asm volatile("mbarrier.arrive.expect_tx.shared.b64 _, [%0], %1;"
                 :: "r"(a), "r"(bytes) : "memory");
}
__device__ __forceinline__ void mbar_tx_only(uint32_t a, uint32_t bytes) {
    asm volatile("mbarrier.expect_tx.shared.b64 [%0], %1;"
                 :: "r"(a), "r"(bytes) : "memory");
}
__device__ __forceinline__ void mbar_wait(uint32_t a, uint32_t phase) {
    uint32_t done = 0;
    while (!done) {
        asm volatile(
            "{ .reg .pred p; mbarrier.try_wait.parity.shared.b64 p, [%1], %2; "
            "selp.b32 %0, 1, 0, p; }"
            : "=r"(done) : "r"(a), "r"(phase) : "memory");
    }
}
__device__ __forceinline__ void bulk_g2s(uint32_t dst, const void* src,
                                         uint32_t bytes, uint32_t mbar) {
    asm volatile(
        "cp.async.bulk.shared::cluster.global.mbarrier::complete_tx::bytes "
        "[%0], [%1], %2, [%3];"
        :: "r"(dst), "l"(src), "r"(bytes), "r"(mbar) : "memory");
}
__device__ __forceinline__ uint64_t mkdesc(uint32_t addr) {
    return ((uint64_t)2 << 61) | ((uint64_t)1 << 46) | ((uint64_t)64 << 32)
         | ((uint64_t)1 << 16) | ((addr >> 4) & 0x3FFF);
}
#define GEMM_IDESC ((1u<<4) | (1u<<7) | (1u<<10) | ((TN/8)<<17) | ((128/16)<<24))
#define GDC_WAIT()   asm volatile("griddepcontrol.wait;" ::: "memory")
#define GDC_LAUNCH() asm volatile("griddepcontrol.launch_dependents;" ::: "memory")

__device__ __forceinline__ float bfbits2f(uint16_t u) {
    __nv_bfloat16_raw r; r.x = u;
    return __bfloat162float(__nv_bfloat16(r));
}
__device__ __forceinline__ uint16_t f2bfbits(float f) {
    __nv_bfloat16 h = __float2bfloat16(f);
    __nv_bfloat16_raw r = (__nv_bfloat16_raw)h;
    return r.x;
}

#if HAS_TCGEN05
__device__ __forceinline__ void mma_f16_ss(uint32_t d, uint64_t a, uint64_t b,
                                           uint32_t idesc, uint32_t en) {
    asm volatile(
        "{\n\t.reg .pred p;\n\tsetp.ne.u32 p, %5, 0;\n\t"
        "tcgen05.mma.cta_group::1.kind::f16 [%0], %1, %2, %3, {%4,%4,%4,%4}, p;\n\t}"
        :: "r"(d), "l"(a), "l"(b), "r"(idesc), "r"(0u), "r"(en) : "memory");
}
__device__ __forceinline__ void tc_commit(uint32_t mbar) {
    asm volatile(
        "tcgen05.commit.cta_group::1.mbarrier::arrive::one.shared::cluster.b64 [%0];"
        :: "r"(mbar) : "memory");
}
#define TC_ALLOC(sres, n) \
    asm volatile("tcgen05.alloc.cta_group::1.sync.aligned.shared::cta.b32 [%0], %1;" \
                 :: "r"(sres), "r"((uint32_t)(n)) : "memory")
#define TC_RELINQ() \
    asm volatile("tcgen05.relinquish_alloc_permit.cta_group::1.sync.aligned;")
#define TC_DEALLOC(t, n) \
    asm volatile("tcgen05.dealloc.cta_group::1.sync.aligned.b32 %0, %1;" :: "r"(t), "r"((uint32_t)(n)))
#define TC_FENCE_AFTER()  asm volatile("tcgen05.fence::after_thread_sync;" ::: "memory")
#define TC_WAIT_LD()      asm volatile("tcgen05.wait::ld.sync.aligned;" ::: "memory")
#define LDTM_X32(r, a) \
    asm volatile( \
        "tcgen05.ld.sync.aligned.32x32b.x32.b32 " \
        "{%0,%1,%2,%3,%4,%5,%6,%7,%8,%9,%10,%11,%12,%13,%14,%15," \
        "%16,%17,%18,%19,%20,%21,%22,%23,%24,%25,%26,%27,%28,%29,%30,%31}, [%32];" \
        : "=r"((r)[0]),"=r"((r)[1]),"=r"((r)[2]),"=r"((r)[3]), \
          "=r"((r)[4]),"=r"((r)[5]),"=r"((r)[6]),"=r"((r)[7]), \
          "=r"((r)[8]),"=r"((r)[9]),"=r"((r)[10]),"=r"((r)[11]), \
          "=r"((r)[12]),"=r"((r)[13]),"=r"((r)[14]),"=r"((r)[15]), \
          "=r"((r)[16]),"=r"((r)[17]),"=r"((r)[18]),"=r"((r)[19]), \
          "=r"((r)[20]),"=r"((r)[21]),"=r"((r)[22]),"=r"((r)[23]), \
          "=r"((r)[24]),"=r"((r)[25]),"=r"((r)[26]),"=r"((r)[27]), \
          "=r"((r)[28]),"=r"((r)[29]),"=r"((r)[30]),"=r"((r)[31]) \
        : "r"(a))
#endif  // HAS_TCGEN05

// ---------------------------------------------------------------------------
// PGD iteration: PDL + warp-specialized producer/consumer.
//   tid 32 (producer): early Q loads pre-wait; lam loads post-wait; stage refills
//   tid 0  (consumer): full-waits + MMA issue + commits
// ---------------------------------------------------------------------------
__global__ void __launch_bounds__(256, 1) pgd_pdl(
    const __nv_bfloat16* __restrict__ Ahi, const __nv_bfloat16* __restrict__ Alo,
    const __nv_bfloat16* __restrict__ Bhi, const __nv_bfloat16* __restrict__ Blo,
    const float* __restrict__ cc, const float* __restrict__ act,
    __nv_bfloat16* __restrict__ ohi, __nv_bfloat16* __restrict__ olo,
    int masked)
{
#if HAS_TCGEN05
    extern __shared__ char draw[];
    const uint32_t dsm = (s2u(draw) + 1023u) & ~1023u;

    __shared__ uint32_t s_tmem;
    __shared__ __align__(8) uint64_t s_bar[5];

    const int tid  = threadIdx.x;
    const int wid  = tid >> 5;
    const int lane = tid & 31;
    const int bm0  = blockIdx.y * TM;
    const int bn0  = blockIdx.x * TN;

    const uint32_t f0 = s2u(&s_bar[0]);
    const uint32_t f1 = s2u(&s_bar[1]);
    const uint32_t e0 = s2u(&s_bar[2]);
    const uint32_t e1 = s2u(&s_bar[3]);
    const uint32_t db = s2u(&s_bar[4]);

    if (wid == 0) TC_ALLOC(s2u(&s_tmem), 256);
    if (tid == 0) {
        mbar_init(f0, 1); mbar_init(f1, 1);
        mbar_init(e0, 1); mbar_init(e1, 1);
        mbar_init(db, 1);
    }
    __syncthreads();
    uint32_t tmem;
    asm volatile("ld.shared.b32 %0, [%1];" : "=r"(tmem) : "r"(s2u(&s_tmem)));

    const char* aH = (const char*)Ahi + (size_t)blockIdx.y * 16 * TILEA_B;
    const char* aL = (const char*)Alo + (size_t)blockIdx.y * 16 * TILEA_B;
    const char* bH = (const char*)Bhi + (size_t)blockIdx.x * 16 * TILEB_B;
    const char* bL = (const char*)Blo + (size_t)blockIdx.x * 16 * TILEB_B;

    // ---- producer: early Q loads (pre-wait; Q is iteration-invariant) ----
    if (tid == 32) {
#pragma unroll
        for (int ch = 0; ch < 2; ch++) {
            const uint32_t fb = ch ? f1 : f0;
            const uint32_t st = dsm + (uint32_t)ch * STG_SZ;
            mbar_tx_only(fb, 2 * TILEB_B);
            bulk_g2s(st + OFF_BHI, bH + (size_t)ch * TILEB_B, TILEB_B, fb);
            bulk_g2s(st + OFF_BLO, bL + (size_t)ch * TILEB_B, TILEB_B, fb);
        }
    }

    // all threads: wait for predecessor's lam/c/act writes
    GDC_WAIT();

    // ---- producer: lam loads for stages 0,1 then stage refills ----
    if (tid == 32) {
#pragma unroll
        for (int ch = 0; ch < 2; ch++) {
            const uint32_t fb = ch ? f1 : f0;
            const uint32_t st = dsm + (uint32_t)ch * STG_SZ;
            mbar_arrive_tx(fb, 2 * TILEA_B);
            bulk_g2s(st,           aH + (size_t)ch * TILEA_B, TILEA_B, fb);
            bulk_g2s(st + OFF_ALO, aL + (size_t)ch * TILEA_B, TILEA_B, fb);
        }
        uint32_t phe[2] = {0, 0};
#pragma unroll 1
        for (int nx = 2; nx < 16; nx++) {
            const int s = nx & 1;
            mbar_wait(s ? e1 : e0, phe[s]); phe[s] ^= 1;
            const uint32_t fb = s ? f1 : f0;
            const uint32_t st = dsm + (uint32_t)s * STG_SZ;
            mbar_arrive_tx(fb, (uint32_t)STG_SZ);
            bulk_g2s(st,           aH + (size_t)nx * TILEA_B, TILEA_B, fb);
            bulk_g2s(st + OFF_ALO, aL + (size_t)nx * TILEA_B, TILEA_B, fb);
            bulk_g2s(st + OFF_BHI, bH + (size_t)nx * TILEB_B, TILEB_B, fb);
            bulk_g2s(st + OFF_BLO, bL + (size_t)nx * TILEB_B, TILEB_B, fb);
        }
    }

    // ---- consumer: MMA issue ----
    if (tid == 0) {
        uint32_t phf[2] = {0, 0};
#pragma unroll 1
        for (int ch = 0; ch < 16; ch++) {
            const int s = ch & 1;
            mbar_wait(s ? f1 : f0, phf[s]); phf[s] ^= 1;

            const uint32_t st = dsm + (uint32_t)s * STG_SZ;
            const uint64_t dah = mkdesc(st);
            const uint64_t dal = mkdesc(st + OFF_ALO);
            const uint64_t dbh = mkdesc(st + OFF_BHI);
            const uint64_t dbl = mkdesc(st + OFF_BLO);
#pragma unroll
            for (int ks = 0; ks < 4; ks++) {
                mma_f16_ss(tmem, dah + ks * 2, dbh + ks * 2, GEMM_IDESC,
                           (ch == 0 && ks == 0) ? 0u : 1u);
                mma_f16_ss(tmem, dah + ks * 2, dbl + ks * 2, GEMM_IDESC, 1u);
                mma_f16_ss(tmem, dal + ks * 2, dbh + ks * 2, GEMM_IDESC, 1u);
            }
            tc_commit(s ? e1 : e0);
        }
        tc_commit(db);
    }

    mbar_wait(db, 0);
    TC_FENCE_AFTER();

    // ---------------- fused epilogue (operands gathered before TMEM wait) ----
    const int sp   = wid & 3;
    const int half = wid >> 2;
    const int lr   = sp * 32 + lane;
    const int r    = bm0 + lr;

#pragma unroll 1
    for (int cb = 0; cb < 128; cb += 32) {
        uint32_t dreg[32];
        LDTM_X32(dreg, tmem + half * 128 + cb);

        const int coff = half * 128 + cb;
        const int gch  = (bn0 + coff) >> 6;
        const int lc0  = coff & 63;
        const size_t tb = ((size_t)(blockIdx.y * 16 + gch)) * TILEA_B;
        const size_t blin = (size_t)r * Mm + bn0 + coff;

        float4   cv[8];
        uint64_t h4[8], l4[8];
        float4   av[8];
        uint32_t boff[8];
#pragma unroll
        for (int g = 0; g < 8; g++) {
            const int j0 = g * 4;
            boff[g] = swz((uint32_t)(lr * 128 + (lc0 + j0) * 2));
            cv[g] = *(const float4*)&cc[blin + j0];
            h4[g] = *(const uint64_t*)((const char*)Ahi + tb + boff[g]);
            l4[g] = *(const uint64_t*)((const char*)Alo + tb + boff[g]);
            if (masked) av[g] = *(const float4*)&act[blin + j0];
        }

        TC_WAIT_LD();

#pragma unroll
        for (int g = 0; g < 8; g++) {
            const int j0 = g * 4;
            const float* cvp = (const float*)&cv[g];
            const float* avp = (const float*)&av[g];
            uint16_t oh[4], ol[4];
#pragma unroll
            for (int k = 0; k < 4; k++) {
                float lamold = bfbits2f((uint16_t)(h4[g] >> (16 * k)))
                             + bfbits2f((uint16_t)(l4[g] >> (16 * k)));
                float acc = __uint_as_float(dreg[j0 + k]);
                float v = fmaxf(lamold - STEPC * (acc - cvp[k]), 0.f);
                if (masked) v *= avp[k];
                uint16_t hb = f2bfbits(v);
                oh[k] = hb;
                ol[k] = f2bfbits(v - bfbits2f(hb));
            }
            *(uint64_t*)((char*)ohi + tb + boff[g]) =
                (uint64_t)oh[0] | ((uint64_t)oh[1] << 16)
                | ((uint64_t)oh[2] << 32) | ((uint64_t)oh[3] << 48);
            *(uint64_t*)((char*)olo + tb + boff[g]) =
                (uint64_t)ol[0] | ((uint64_t)ol[1] << 16)
                | ((uint64_t)ol[2] << 32) | ((uint64_t)ol[3] << 48);
        }
    }

    GDC_LAUNCH();

    __syncthreads();
    if (wid == 0) { TC_RELINQ(); TC_DEALLOC(tmem, 256); }
#endif  // HAS_TCGEN05
}

// epilogue variants (cg1 peripheral GEMMs)
enum { E_C = 0, E_ACT, E_MSK, E_Z, E_OUT, E_Q };

// ---------------------------------------------------------------------------
// Generic cg1 tcgen05 GEMM, fused epilogues, optional PDL early loads.
//   early bit0: A operand is pre-chain-safe (load before griddepcontrol.wait)
//   early bit1: B operand is pre-chain-safe
// ---------------------------------------------------------------------------
template <int EPI>
__global__ void __launch_bounds__(256, 1) tc_gemm(
    const __nv_bfloat16* __restrict__ Ahi, const __nv_bfloat16* __restrict__ Alo,
    const __nv_bfloat16* __restrict__ Bhi, const __nv_bfloat16* __restrict__ Blo,
    int nch,
    const float* __restrict__ v1, const float* __restrict__ v2,
    float* __restrict__ o32,
    __nv_bfloat16* __restrict__ ohi, __nv_bfloat16* __restrict__ olo,
    int Ncols, int early)
{
#if HAS_TCGEN05
    extern __shared__ char draw[];
    const uint32_t dsm = (s2u(draw) + 1023u) & ~1023u;

    __shared__ uint32_t s_tmem;
    __shared__ __align__(8) uint64_t s_bar[5];

    const int tid  = threadIdx.x;
    const int wid  = tid >> 5;
    const int lane = tid & 31;
    const int bm0  = blockIdx.y * TM;
    const int bn0  = blockIdx.x * TN;

    const uint32_t f0 = s2u(&s_bar[0]);
    const uint32_t f1 = s2u(&s_bar[1]);
    const uint32_t e0 = s2u(&s_bar[2]);
    const uint32_t e1 = s2u(&s_bar[3]);
    const uint32_t db = s2u(&s_bar[4]);

    if (wid == 0) TC_ALLOC(s2u(&s_tmem), 256);
    if (tid == 0) {
        mbar_init(f0, 1); mbar_init(f1, 1);
        mbar_init(e0, 1); mbar_init(e1, 1);
        mbar_init(db, 1);
    }
    __syncthreads();
    uint32_t tmem;
    asm volatile("ld.shared.b32 %0, [%1];" : "=r"(tmem) : "r"(s2u(&s_tmem)));

    const int earlyA = early & 1, earlyB = early & 2;
    const char* aH = (const char*)Ahi + (size_t)blockIdx.y * nch * TILEA_B;
    const char* aL = (const char*)Alo + (size_t)blockIdx.y * nch * TILEA_B;
    const char* bH = (const char*)Bhi + (size_t)blockIdx.x * nch * TILEB_B;
    const char* bL = (const char*)Blo + (size_t)blockIdx.x * nch * TILEB_B;

    // pre-wait loads for chain-safe operands
    if (tid == 0 && earlyB) {
#pragma unroll
        for (int ch = 0; ch < 2; ch++) {
            const uint32_t fb = ch ? f1 : f0;
            const uint32_t st = dsm + (uint32_t)ch * STG_SZ;
            mbar_tx_only(fb, 2 * TILEB_B);
            bulk_g2s(st + OFF_BHI, bH + (size_t)ch * TILEB_B, TILEB_B, fb);
            bulk_g2s(st + OFF_BLO, bL + (size_t)ch * TILEB_B, TILEB_B, fb);
        }
    }
    if (tid == 0 && earlyA) {
#pragma unroll
        for (int ch = 0; ch < 2; ch++) {
            const uint32_t fb = ch ? f1 : f0;
            const uint32_t st = dsm + (uint32_t)ch * STG_SZ;
            mbar_arrive_tx(fb, earlyB ? 2 * TILEA_B : (uint32_t)STG_SZ);
            bulk_g2s(st,           aH + (size_t)ch * TILEA_B, TILEA_B, fb);
            bulk_g2s(st + OFF_ALO, aL + (size_t)ch * TILEA_B, TILEA_B, fb);
            if (!earlyB) {
                bulk_g2s(st + OFF_BHI, bH + (size_t)ch * TILEB_B, TILEB_B, fb);
                bulk_g2s(st + OFF_BLO, bL + (size_t)ch * TILEB_B, TILEB_B, fb);
            }
        }
    }
    if (!earlyA) {
        GDC_WAIT();
        if (tid == 0) {
#pragma unroll
            for (int ch = 0; ch < 2; ch++) {
                const uint32_t fb = ch ? f1 : f0;
                const uint32_t st = dsm + (uint32_t)ch * STG_SZ;
                mbar_arrive_tx(fb, earlyB ? 2 * TILEA_B : (uint32_t)STG_SZ);
                bulk_g2s(st,           aH + (size_t)ch * TILEA_B, TILEA_B, fb);
                bulk_g2s(st + OFF_ALO, aL + (size_t)ch * TILEA_B, TILEA_B, fb);
                if (!earlyB) {
                    bulk_g2s(st + OFF_BHI, bH + (size_t)ch * TILEB_B, TILEB_B, fb);
                    bulk_g2s(st + OFF_BLO, bL + (size_t)ch * TILEB_B, TILEB_B, fb);
                }
            }
        }
    }

    if (tid == 0) {
        uint32_t phf[2] = {0, 0}, phe[2] = {0, 0};
#pragma unroll 1
        for (int ch = 0; ch < nch; ch++) {
            const int s = ch & 1;
            mbar_wait(s ? f1 : f0, phf[s]); phf[s] ^= 1;

            const uint32_t st = dsm + (uint32_t)s * STG_SZ;
            const uint64_t dah = mkdesc(st);
            const uint64_t dal = mkdesc(st + OFF_ALO);
            const uint64_t dbh = mkdesc(st + OFF_BHI);
            const uint64_t dbl = mkdesc(st + OFF_BLO);
#pragma unroll
            for (int ks = 0; ks < 4; ks++) {
                mma_f16_ss(tmem, dah + ks * 2, dbh + ks * 2, GEMM_IDESC,
                           (ch == 0 && ks == 0) ? 0u : 1u);
                mma_f16_ss(tmem, dah + ks * 2, dbl + ks * 2, GEMM_IDESC, 1u);
                mma_f16_ss(tmem, dal + ks * 2, dbh + ks * 2, GEMM_IDESC, 1u);
            }
            tc_commit(s ? e1 : e0);

            if (ch + 2 < nch) {
                mbar_wait(s ? e1 : e0, phe[s]); phe[s] ^= 1;
                const int nx = ch + 2;
                const uint32_t fb = s ? f1 : f0;
                const uint32_t st2 = dsm + (uint32_t)s * STG_SZ;
                mbar_arrive_tx(fb, (uint32_t)STG_SZ);
                bulk_g2s(st2,           aH + (size_t)nx * TILEA_B, TILEA_B, fb);
                bulk_g2s(st2 + OFF_ALO, aL + (size_t)nx * TILEA_B, TILEA_B, fb);
                bulk_g2s(st2 + OFF_BHI, bH + (size_t)nx * TILEB_B, TILEB_B, fb);
                bulk_g2s(st2 + OFF_BLO, bL + (size_t)nx * TILEB_B, TILEB_B, fb);
            }
        }
        tc_commit(db);
    }

    mbar_wait(db, 0);
    if (earlyA) GDC_WAIT();   // chain ordering before epilogue reads (e.g. act)
    TC_FENCE_AFTER();

    const int sp   = wid & 3;
    const int half = wid >> 2;
    const int lr   = sp * 32 + lane;
    const int r    = bm0 + lr;
    const int nchO = Ncols >> 6;

#pragma unroll 1
    for (int cb = 0; cb < 128; cb += 32) {
        uint32_t dreg[32];
        LDTM_X32(dreg, tmem + half * 128 + cb);
        TC_WAIT_LD();

        const int coff = half * 128 + cb;
        const int gch  = (bn0 + coff) >> 6;
        const int lc0  = coff & 63;
        const size_t blin = (size_t)r * Ncols + bn0 + coff;
        const size_t tbA = ((size_t)(blockIdx.y * nchO + gch)) * TILEA_B;
        const size_t tbB = ((size_t)((r >> 8) * nchO + gch)) * TILEB_B;
        const int brow = r & 255;

#pragma unroll
        for (int j0 = 0; j0 < 32; j0 += 4) {
            const uint32_t boffA = swz((uint32_t)(lr * 128 + (lc0 + j0) * 2));
            float res[4];
#pragma unroll
            for (int k = 0; k < 4; k++) res[k] = __uint_as_float(dreg[j0 + k]);

            if (EPI == E_C) {
                float4 bv = *(const float4*)&v1[bn0 + coff + j0];
                const float* bp = (const float*)&bv;
                uint16_t oh[4], ol[4];
                float cvv[4];
#pragma unroll
                for (int k = 0; k < 4; k++) {
                    float cv = res[k] - bp[k];
                    cvv[k] = cv;
                    float v = fmaxf(STEPC * cv, 0.f);
                    uint16_t hb = f2bfbits(v);
                    oh[k] = hb; ol[k] = f2bfbits(v - bfbits2f(hb));
                }
                *(float4*)&o32[blin + j0] = make_float4(cvv[0], cvv[1], cvv[2], cvv[3]);
                *(uint64_t*)((char*)ohi + tbA + boffA) =
                    (uint64_t)oh[0] | ((uint64_t)oh[1] << 16)
                    | ((uint64_t)oh[2] << 32) | ((uint64_t)oh[3] << 48);
                *(uint64_t*)((char*)olo + tbA + boffA) =
                    (uint64_t)ol[0] | ((uint64_t)ol[1] << 16)
                    | ((uint64_t)ol[2] << 32) | ((uint64_t)ol[3] << 48);
            } else if (EPI == E_ACT) {
                float4 bv = *(const float4*)&v1[bn0 + coff + j0];
                const float* bp = (const float*)&bv;
                float o[4];
#pragma unroll
                for (int k = 0; k < 4; k++)
                    o[k] = (res[k] >= bp[k] - TOLV) ? 1.f : 0.f;
                *(float4*)&o32[blin + j0] = make_float4(o[0], o[1], o[2], o[3]);
            } else if (EPI == E_MSK) {
                float4 avv = *(const float4*)&v1[blin + j0];
                const float* ap = (const float*)&avv;
                uint16_t oh[4], ol[4];
                float mm[4];
#pragma unroll
                for (int k = 0; k < 4; k++) {
                    float m = res[k] * ap[k];
                    mm[k] = m;
                    float v = fmaxf(STEPC * m, 0.f) * ap[k];
                    uint16_t hb = f2bfbits(v);
                    oh[k] = hb; ol[k] = f2bfbits(v - bfbits2f(hb));
                }
                *(float4*)&o32[blin + j0] = make_float4(mm[0], mm[1], mm[2], mm[3]);
                *(uint64_t*)((char*)ohi + tbA + boffA) =
                    (uint64_t)oh[0] | ((uint64_t)oh[1] << 16)
                    | ((uint64_t)oh[2] << 32) | ((uint64_t)oh[3] << 48);
                *(uint64_t*)((char*)olo + tbA + boffA) =
                    (uint64_t)ol[0] | ((uint64_t)ol[1] << 16)
                    | ((uint64_t)ol[2] << 32) | ((uint64_t)ol[3] << 48);
            } else if (EPI == E_Z) {
                float4 xv = *(const float4*)&v1[blin + j0];
                float4 uv = *(const float4*)&v2[blin + j0];
                const float* xp = (const float*)&xv;
                const float* up = (const float*)&uv;
                uint16_t oh[4], ol[4];
#pragma unroll
                for (int k = 0; k < 4; k++) {
                    float zv = xp[k] + up[k] - res[k];
                    uint16_t hb = f2bfbits(zv);
                    oh[k] = hb; ol[k] = f2bfbits(zv - bfbits2f(hb));
                }
                *(uint64_t*)((char*)ohi + tbA + boffA) =
                    (uint64_t)oh[0] | ((uint64_t)oh[1] << 16)
                    | ((uint64_t)oh[2] << 32) | ((uint64_t)oh[3] << 48);
                *(uint64_t*)((char*)olo + tbA + boffA) =
                    (uint64_t)ol[0] | ((uint64_t)ol[1] << 16)
                    | ((uint64_t)ol[2] << 32) | ((uint64_t)ol[3] << 48);
            } else if (EPI == E_OUT) {
                float4 uv = *(const float4*)&v1[blin + j0];
                const float* up = (const float*)&uv;
                float o[4];
#pragma unroll
                for (int k = 0; k < 4; k++) o[k] = up[k] - res[k];
                *(float4*)&o32[blin + j0] = make_float4(o[0], o[1], o[2], o[3]);
            } else if (EPI == E_Q) {
                const uint32_t boffB = swz((uint32_t)(brow * 128 + (lc0 + j0) * 2));
                uint16_t oh[4], ol[4];
#pragma unroll
                for (int k = 0; k < 4; k++) {
                    uint16_t hb = f2bfbits(res[k]);
                    oh[k] = hb; ol[k] = f2bfbits(res[k] - bfbits2f(hb));
                }
                *(uint64_t*)((char*)ohi + tbB + boffB) =
                    (uint64_t)oh[0] | ((uint64_t)oh[1] << 16)
                    | ((uint64_t)oh[2] << 32) | ((uint64_t)oh[3] << 48);
                *(uint64_t*)((char*)olo + tbB + boffB) =
                    (uint64_t)ol[0] | ((uint64_t)ol[1] << 16)
                    | ((uint64_t)ol[2] << 32) | ((uint64_t)ol[3] << 48);
            }
        }
    }

    GDC_LAUNCH();

    __syncthreads();
    if (wid == 0) { TC_RELINQ(); TC_DEALLOC(tmem, 256); }
#endif  // HAS_TCGEN05
}

// ---------------- prep kernels ----------------
__device__ __forceinline__ void img_store(__nv_bfloat16* hi, __nv_bfloat16* lo,
                                          size_t tb, uint32_t boff, float v)
{
    __nv_bfloat16 h = __float2bfloat16(v);
    *(__nv_bfloat16*)((char*)hi + tb + boff) = h;
    *(__nv_bfloat16*)((char*)lo + tb + boff) = __float2bfloat16(v - __bfloat162float(h));
}

__global__ void split_A_images(const float* __restrict__ A)
{
    int i = blockIdx.x * blockDim.x + threadIdx.x;
    if (i >= Mm * Nn) return;
    int r = i >> 9, k = i & 511;
    float v = A[i];
    int ch = k >> 6, lc = k & 63;
    {
        int bm = r >> 7, lrow = r & 127;
        size_t tb = ((size_t)(bm * 8 + ch)) * TILEA_B;
        img_store(g_AAi_h, g_AAi_l, tb, swz((uint32_t)(lrow * 128 + lc * 2)), v);
    }
    {
        int nb = r >> 8, brow = r & 255;
        size_t tb = ((size_t)(nb * 8 + ch)) * TILEB_B;
        img_store(g_ABi_h, g_ABi_l, tb, swz((uint32_t)(brow * 128 + lc * 2)), v);
    }
}

__global__ void split_AT_image(const float* __restrict__ A)
{
    int i = blockIdx.x * blockDim.x + threadIdx.x;
    if (i >= Nn * Mm) return;
    int n = i >> 10, k = i & 1023;
    float v = A[(size_t)k * Nn + n];
    int nb = n >> 8, brow = n & 255, ch = k >> 6, lc = k & 63;
    size_t tb = ((size_t)(nb * 16 + ch)) * TILEB_B;
    img_store(g_ATi_h, g_ATi_l, tb, swz((uint32_t)(brow * 128 + lc * 2)), v);
}

__global__ void split_xu_u(const float* __restrict__ x, const float* __restrict__ u)
{
    int i = blockIdx.x * blockDim.x + threadIdx.x;
    if (i >= Bsz * Nn) return;
    int r = i >> 9, k = i & 511;
    int bm = r >> 7, lrow = r & 127, ch = k >> 6, lc = k & 63;
    size_t tb = ((size_t)(bm * 8 + ch)) * TILEA_B;
    uint32_t boff = swz((uint32_t)(lrow * 128 + lc * 2));
    float uv = u[i];
    img_store(g_xu_h, g_xu_l, tb, boff, x[i] + uv);
    img_store(g_u_h,  g_u_l,  tb, boff, uv);
}

// ---------------------------------------------------------------------------
extern "C" void kernel_launch(void* const* d_in, const int* in_sizes, int n_in,
                              void* d_out, int out_size)
{
    const float* x = (const float*)d_in[0];
    const float* u = (const float*)d_in[1];
    const float* A = (const float*)d_in[2];
    const float* b = (const float*)d_in[3];
    float* out = (float*)d_out;

    float *c, *msk, *act;
    __nv_bfloat16 *AAh, *AAl, *ABh, *ABl, *ATh, *ATl, *XUh, *XUl, *Uh, *Ul,
                  *Zh, *Zl, *Qh, *Ql, *lAh, *lAl, *lBh, *lBl;
    cudaGetSymbolAddress((void**)&c,   g_c);
    cudaGetSymbolAddress((void**)&msk, g_msk);
    cudaGetSymbolAddress((void**)&act, g_act);
    cudaGetSymbolAddress((void**)&AAh, g_AAi_h); cudaGetSymbolAddress((void**)&AAl, g_AAi_l);
    cudaGetSymbolAddress((void**)&ABh, g_ABi_h); cudaGetSymbolAddress((void**)&ABl, g_ABi_l);
    cudaGetSymbolAddress((void**)&ATh, g_ATi_h); cudaGetSymbolAddress((void**)&ATl, g_ATi_l);
    cudaGetSymbolAddress((void**)&XUh, g_xu_h);  cudaGetSymbolAddress((void**)&XUl, g_xu_l);
    cudaGetSymbolAddress((void**)&Uh,  g_u_h);   cudaGetSymbolAddress((void**)&Ul,  g_u_l);
    cudaGetSymbolAddress((void**)&Zh,  g_z_h);   cudaGetSymbolAddress((void**)&Zl,  g_z_l);
    cudaGetSymbolAddress((void**)&Qh,  g_Qhi);   cudaGetSymbolAddress((void**)&Ql,  g_Qlo);
    cudaGetSymbolAddress((void**)&lAh, g_lAhi);  cudaGetSymbolAddress((void**)&lAl, g_lAlo);
    cudaGetSymbolAddress((void**)&lBh, g_lBhi);  cudaGetSymbolAddress((void**)&lBl, g_lBlo);

    cudaFuncSetAttribute(tc_gemm<E_C>,   cudaFuncAttributeMaxDynamicSharedMemorySize, DSMEM);
    cudaFuncSetAttribute(tc_gemm<E_ACT>, cudaFuncAttributeMaxDynamicSharedMemorySize, DSMEM);
    cudaFuncSetAttribute(tc_gemm<E_MSK>, cudaFuncAttributeMaxDynamicSharedMemorySize, DSMEM);
    cudaFuncSetAttribute(tc_gemm<E_Z>,   cudaFuncAttributeMaxDynamicSharedMemorySize, DSMEM);
    cudaFuncSetAttribute(tc_gemm<E_OUT>, cudaFuncAttributeMaxDynamicSharedMemorySize, DSMEM);
    cudaFuncSetAttribute(tc_gemm<E_Q>,   cudaFuncAttributeMaxDynamicSharedMemorySize, DSMEM);
    cudaFuncSetAttribute(pgd_pdl,        cudaFuncAttributeMaxDynamicSharedMemorySize, DSMEM);

    const dim3 blk(256);
    const int EW = 256;

    // prep (plain launches — first in chain)
    split_A_images<<<(Mm * Nn + EW - 1) / EW, EW>>>(A);
    split_AT_image<<<(Nn * Mm + EW - 1) / EW, EW>>>(A);
    split_xu_u<<<(int)(((size_t)Bsz * Nn + EW - 1) / EW), EW>>>(x, u);

    // PDL config (grid mutated per launch)
    cudaLaunchAttribute pdlAttr;
    pdlAttr.id = cudaLaunchAttributeProgrammaticStreamSerialization;
    pdlAttr.val.programmaticStreamSerializationAllowed = 1;
    cudaLaunchConfig_t cfg = {};
    cfg.blockDim = blk;
    cfg.dynamicSmemBytes = DSMEM;
    cfg.stream = 0;
    cfg.attrs = &pdlAttr;
    cfg.numAttrs = 1;

    // Q = A @ A^T -> Q B-images (conservative: operands from prep = predecessor)
    cfg.gridDim = dim3(4, 8);
    cudaLaunchKernelEx(&cfg, tc_gemm<E_Q>,
                       (const __nv_bfloat16*)AAh, (const __nv_bfloat16*)AAl,
                       (const __nv_bfloat16*)ABh, (const __nv_bfloat16*)ABl, 8,
                       (const float*)nullptr, (const float*)nullptr,
                       (float*)nullptr, Qh, Ql, 1024, 0);

    // c = xu @ A^T - b (+ lam init): operands from prep, transitively visible -> early=3
    cfg.gridDim = dim3(4, 32);
    cudaLaunchKernelEx(&cfg, tc_gemm<E_C>,
                       (const __nv_bfloat16*)XUh, (const __nv_bfloat16*)XUl,
                       (const __nv_bfloat16*)ABh, (const __nv_bfloat16*)ABl, 8,
                       (const float*)b, (const float*)nullptr,
                       c, lAh, lAl, 1024, 3);

    // PGD iters 2..50 (49 PDL launches, warp-specialized)
    cfg.gridDim = dim3(4, 32);
    __nv_bfloat16 *curh = lAh, *curl = lAl, *nxth = lBh, *nxtl = lBl;
    for (int it = 1; it < 50; it++) {
        cudaLaunchKernelEx(&cfg, pgd_pdl,
                           (const __nv_bfloat16*)curh, (const __nv_bfloat16*)curl,
                           (const __nv_bfloat16*)Qh,  (const __nv_bfloat16*)Ql,
                           (const float*)c, (const float*)nullptr,
                           nxth, nxtl, 0);
        __nv_bfloat16* t;
        t = curh; curh = nxth; nxth = t;
        t = curl; curl = nxtl; nxtl = t;
    }

    // z = x + u - lam @ A  (A = lam from pred -> earlyB only)
    cfg.gridDim = dim3(2, 32);
    cudaLaunchKernelEx(&cfg, tc_gemm<E_Z>,
                       (const __nv_bfloat16*)curh, (const __nv_bfloat16*)curl,
                       (const __nv_bfloat16*)ATh, (const __nv_bfloat16*)ATl, 16,
                       (const float*)x, (const float*)u,
                       (float*)nullptr, Zh, Zl, 512, 2);
    // active  (A = z from pred -> earlyB only)
    cfg.gridDim = dim3(4, 32);
    cudaLaunchKernelEx(&cfg, tc_gemm<E_ACT>,
                       (const __nv_bfloat16*)Zh, (const __nv_bfloat16*)Zl,
                       (const __nv_bfloat16*)ABh, (const __nv_bfloat16*)ABl, 8,
                       (const float*)b, (const float*)nullptr,
                       act, (__nv_bfloat16*)nullptr, (__nv_bfloat16*)nullptr, 1024, 2);
    // masked (+ masked lam init): both operands prep-constant -> early=3
    cfg.gridDim = dim3(4, 32);
    cudaLaunchKernelEx(&cfg, tc_gemm<E_MSK>,
                       (const __nv_bfloat16*)Uh, (const __nv_bfloat16*)Ul,
                       (const __nv_bfloat16*)ABh, (const __nv_bfloat16*)ABl, 8,
                       (const float*)act, (const float*)nullptr,
                       msk, lAh, lAl, 1024, 3);

    // masked PGD iters 2..10 (9 PDL launches)
    cfg.gridDim = dim3(4, 32);
    curh = lAh; curl = lAl; nxth = lBh; nxtl = lBl;
    for (int it = 1; it < 10; it++) {
        cudaLaunchKernelEx(&cfg, pgd_pdl,
                           (const __nv_bfloat16*)curh, (const __nv_bfloat16*)curl,
                           (const __nv_bfloat16*)Qh,  (const __nv_bfloat16*)Ql,
                           (const float*)msk, (const float*)act,
                           nxth, nxtl, 1);
        __nv_bfloat16* t;
        t = curh; curh = nxth; nxth = t;
        t = curl; curl = nxtl; nxtl = t;
    }

    // out = u - lam @ A  (A = lam from pred -> earlyB only)
    cfg.gridDim = dim3(2, 32);
    cudaLaunchKernelEx(&cfg, tc_gemm<E_OUT>,
                       (const __nv_bfloat16*)curh, (const __nv_bfloat16*)curl,
                       (const __nv_bfloat16*)ATh, (const __nv_bfloat16*)ATl, 16,
                       (const float*)u, (const float*)nullptr,
                       out, (__nv_bfloat16*)nullptr, (__nv_bfloat16*)nullptr, 512, 2);
}

// round 13
// speedup vs baseline: 2.2894x; 1.1046x over previous
#include <cuda_runtime.h>
#include <cuda_bf16.h>
#include <cstddef>
#include <cstdint>

// Problem constants (B=4096, n=512, m=1024)
#define Bsz 4096
#define Nn  512
#define Mm  1024
#define STEPC 0.01f
#define INVSTEP 100.0f
#define TOLV 1e-5f

// ---- tensor tile config ----
#define TM 128
#define TN 256
#define KC 64
#define TILEA_B 16384          // 128x64 bf16 tile bytes
#define TILEB_B 32768          // 256x64 bf16 tile bytes
#define OFF_ALO 16384
#define OFF_BHI 32768
#define OFF_BLO 65536
#define STG_SZ  98304          // 96 KB per stage
#define DSMEM   (2 * STG_SZ + 1024)

#if defined(__CUDA_ARCH__) && defined(__CUDA_ARCH_FEAT_SM103_ALL)
#define HAS_TCGEN05 1
#else
#define HAS_TCGEN05 0
#endif

// ---------------- device scratch (allocation-free) ----------------
__device__ __align__(128) float g_c[(size_t)Bsz * Mm];
__device__ __align__(128) float g_msk[(size_t)Bsz * Mm];
__device__ __align__(128) float g_act[(size_t)Bsz * Mm];
__device__ __align__(128) __nv_bfloat16 g_AAi_h[Mm * Nn];   // A as A-image [8][8]
__device__ __align__(128) __nv_bfloat16 g_AAi_l[Mm * Nn];
__device__ __align__(128) __nv_bfloat16 g_ABi_h[Mm * Nn];   // A as B-image [4][8]
__device__ __align__(128) __nv_bfloat16 g_ABi_l[Mm * Nn];
__device__ __align__(128) __nv_bfloat16 g_ATi_h[Nn * Mm];   // A^T as B-image [2][16]
__device__ __align__(128) __nv_bfloat16 g_ATi_l[Nn * Mm];
__device__ __align__(128) __nv_bfloat16 g_xu_h[(size_t)Bsz * Nn];
__device__ __align__(128) __nv_bfloat16 g_xu_l[(size_t)Bsz * Nn];
__device__ __align__(128) __nv_bfloat16 g_u_h[(size_t)Bsz * Nn];
__device__ __align__(128) __nv_bfloat16 g_u_l[(size_t)Bsz * Nn];
__device__ __align__(128) __nv_bfloat16 g_z_h[(size_t)Bsz * Nn];
__device__ __align__(128) __nv_bfloat16 g_z_l[(size_t)Bsz * Nn];
// Q' = Q - (1/step) I as B-image [4 nb][16 ch][256x64, 32 KB]
__device__ __align__(128) __nv_bfloat16 g_Qhi[Mm * Mm];
__device__ __align__(128) __nv_bfloat16 g_Qlo[Mm * Mm];
__device__ __align__(128) __nv_bfloat16 g_lAhi[(size_t)Bsz * Mm]; // lam A-images [32][16]
__device__ __align__(128) __nv_bfloat16 g_lAlo[(size_t)Bsz * Mm];
__device__ __align__(128) __nv_bfloat16 g_lBhi[(size_t)Bsz * Mm];
__device__ __align__(128) __nv_bfloat16 g_lBlo[(size_t)Bsz * Mm];

// ---------------- helpers ----------------
__device__ __forceinline__ uint32_t s2u(const void* p) {
    uint32_t a;
    asm("{ .reg .u64 t; cvta.to.shared.u64 t, %1; cvt.u32.u64 %0, t; }"
        : "=r"(a) : "l"(p));
    return a;
}
__device__ __forceinline__ uint32_t swz(uint32_t off) {
    return off ^ ((off >> 3) & 0x70);
}
__device__ __forceinline__ void mbar_init(uint32_t a, uint32_t cnt) {
    asm volatile("mbarrier.init.shared.b64 [%0], %1;" :: "r"(a), "r"(cnt) : "memory");
}
__device__ __forceinline__ void mbar_arrive_tx(uint32_t a, uint32_t bytes) {
    asm volatile("mbarrier.arrive.expect_tx.shared.b64 _, [%0], %1;"
                 :: "r"(a), "r"(bytes) : "memory");
}
__device__ __forceinline__ void mbar_tx_only(uint32_t a, uint32_t bytes) {
    asm volatile("mbarrier.expect_tx.shared.b64 [%0], %1;"
                 :: "r"(a), "r"(bytes) : "memory");
}
__device__ __forceinline__ void mbar_wait(uint32_t a, uint32_t phase) {
    uint32_t done = 0;
    while (!done) {
        asm volatile(
            "{ .reg .pred p; mbarrier.try_wait.parity.shared.b64 p, [%1], %2; "
            "selp.b32 %0, 1, 0, p; }"
            : "=r"(done) : "r"(a), "r"(phase) : "memory");
    }
}
__device__ __forceinline__ void bulk_g2s(uint32_t dst, const void* src,
                                         uint32_t bytes, uint32_t mbar) {
    asm volatile(
        "cp.async.bulk.shared::cluster.global.mbarrier::complete_tx::bytes "
        "[%0], [%1], %2, [%3];"
        :: "r"(dst), "l"(src), "r"(bytes), "r"(mbar) : "memory");
}
__device__ __forceinline__ uint64_t mkdesc(uint32_t addr) {
    return ((uint64_t)2 << 61) | ((uint64_t)1 << 46) | ((uint64_t)64 << 32)
         | ((uint64_t)1 << 16) | ((addr >> 4) & 0x3FFF);
}
#define GEMM_IDESC ((1u<<4) | (1u<<7) | (1u<<10) | ((TN/8)<<17) | ((128/16)<<24))
#define GDC_WAIT()   asm volatile("griddepcontrol.wait;" ::: "memory")
#define GDC_LAUNCH() asm volatile("griddepcontrol.launch_dependents;" ::: "memory")

__device__ __forceinline__ float bfbits2f(uint16_t u) {
    __nv_bfloat16_raw r; r.x = u;
    return __bfloat162float(__nv_bfloat16(r));
}
__device__ __forceinline__ uint16_t f2bfbits(float f) {
    __nv_bfloat16 h = __float2bfloat16(f);
    __nv_bfloat16_raw r = (__nv_bfloat16_raw)h;
    return r.x;
}

#if HAS_TCGEN05
__device__ __forceinline__ void mma_f16_ss(uint32_t d, uint64_t a, uint64_t b,
                                           uint32_t idesc, uint32_t en) {
    asm volatile(
        "{\n\t.reg .pred p;\n\tsetp.ne.u32 p, %5, 0;\n\t"
        "tcgen05.mma.cta_group::1.kind::f16 [%0], %1, %2, %3, {%4,%4,%4,%4}, p;\n\t}"
        :: "r"(d), "l"(a), "l"(b), "r"(idesc), "r"(0u), "r"(en) : "memory");
}
__device__ __forceinline__ void tc_commit(uint32_t mbar) {
    asm volatile(
        "tcgen05.commit.cta_group::1.mbarrier::arrive::one.shared::cluster.b64 [%0];"
        :: "r"(mbar) : "memory");
}
#define TC_ALLOC(sres, n) \
    asm volatile("tcgen05.alloc.cta_group::1.sync.aligned.shared::cta.b32 [%0], %1;" \
                 :: "r"(sres), "r"((uint32_t)(n)) : "memory")
#define TC_RELINQ() \
    asm volatile("tcgen05.relinquish_alloc_permit.cta_group::1.sync.aligned;")
#define TC_DEALLOC(t, n) \
    asm volatile("tcgen05.dealloc.cta_group::1.sync.aligned.b32 %0, %1;" :: "r"(t), "r"((uint32_t)(n)))
#define TC_FENCE_AFTER()  asm volatile("tcgen05.fence::after_thread_sync;" ::: "memory")
#define TC_WAIT_LD()      asm volatile("tcgen05.wait::ld.sync.aligned;" ::: "memory")
#define LDTM_X32(r, a) \
    asm volatile( \
        "tcgen05.ld.sync.aligned.32x32b.x32.b32 " \
        "{%0,%1,%2,%3,%4,%5,%6,%7,%8,%9,%10,%11,%12,%13,%14,%15," \
        "%16,%17,%18,%19,%20,%21,%22,%23,%24,%25,%26,%27,%28,%29,%30,%31}, [%32];" \
        : "=r"((r)[0]),"=r"((r)[1]),"=r"((r)[2]),"=r"((r)[3]), \
          "=r"((r)[4]),"=r"((r)[5]),"=r"((r)[6]),"=r"((r)[7]), \
          "=r"((r)[8]),"=r"((r)[9]),"=r"((r)[10]),"=r"((r)[11]), \
          "=r"((r)[12]),"=r"((r)[13]),"=r"((r)[14]),"=r"((r)[15]), \
          "=r"((r)[16]),"=r"((r)[17]),"=r"((r)[18]),"=r"((r)[19]), \
          "=r"((r)[20]),"=r"((r)[21]),"=r"((r)[22]),"=r"((r)[23]), \
          "=r"((r)[24]),"=r"((r)[25]),"=r"((r)[26]),"=r"((r)[27]), \
          "=r"((r)[28]),"=r"((r)[29]),"=r"((r)[30]),"=r"((r)[31]) \
        : "r"(a))
#endif  // HAS_TCGEN05

// ---------------------------------------------------------------------------
// PGD iteration with folded Q' = Q - (1/step) I:
//   lam_new = relu(step * (c - lam @ Q'))  [* act]
//   Epilogue needs only c (+act) — no lam_old reads.
//   PDL + warp-specialized producer (tid 32) / consumer (tid 0).
// ---------------------------------------------------------------------------
__global__ void __launch_bounds__(256, 1) pgd_pdl(
    const __nv_bfloat16* __restrict__ Ahi, const __nv_bfloat16* __restrict__ Alo,
    const __nv_bfloat16* __restrict__ Bhi, const __nv_bfloat16* __restrict__ Blo,
    const float* __restrict__ cc, const float* __restrict__ act,
    __nv_bfloat16* __restrict__ ohi, __nv_bfloat16* __restrict__ olo,
    int masked)
{
#if HAS_TCGEN05
    extern __shared__ char draw[];
    const uint32_t dsm = (s2u(draw) + 1023u) & ~1023u;

    __shared__ uint32_t s_tmem;
    __shared__ __align__(8) uint64_t s_bar[5];

    const int tid  = threadIdx.x;
    const int wid  = tid >> 5;
    const int lane = tid & 31;
    const int bm0  = blockIdx.y * TM;
    const int bn0  = blockIdx.x * TN;

    const uint32_t f0 = s2u(&s_bar[0]);
    const uint32_t f1 = s2u(&s_bar[1]);
    const uint32_t e0 = s2u(&s_bar[2]);
    const uint32_t e1 = s2u(&s_bar[3]);
    const uint32_t db = s2u(&s_bar[4]);

    if (wid == 0) TC_ALLOC(s2u(&s_tmem), 256);
    if (tid == 0) {
        mbar_init(f0, 1); mbar_init(f1, 1);
        mbar_init(e0, 1); mbar_init(e1, 1);
        mbar_init(db, 1);
    }
    __syncthreads();
    uint32_t tmem;
    asm volatile("ld.shared.b32 %0, [%1];" : "=r"(tmem) : "r"(s2u(&s_tmem)));

    const char* aH = (const char*)Ahi + (size_t)blockIdx.y * 16 * TILEA_B;
    const char* aL = (const char*)Alo + (size_t)blockIdx.y * 16 * TILEA_B;
    const char* bH = (const char*)Bhi + (size_t)blockIdx.x * 16 * TILEB_B;
    const char* bL = (const char*)Blo + (size_t)blockIdx.x * 16 * TILEB_B;

    // ---- producer: early Q loads (pre-wait; Q' is iteration-invariant) ----
    if (tid == 32) {
#pragma unroll
        for (int ch = 0; ch < 2; ch++) {
            const uint32_t fb = ch ? f1 : f0;
            const uint32_t st = dsm + (uint32_t)ch * STG_SZ;
            mbar_tx_only(fb, 2 * TILEB_B);
            bulk_g2s(st + OFF_BHI, bH + (size_t)ch * TILEB_B, TILEB_B, fb);
            bulk_g2s(st + OFF_BLO, bL + (size_t)ch * TILEB_B, TILEB_B, fb);
        }
    }

    // all threads: wait for predecessor's lam/c/act writes
    GDC_WAIT();

    // ---- producer: lam loads for stages 0,1 then stage refills ----
    if (tid == 32) {
#pragma unroll
        for (int ch = 0; ch < 2; ch++) {
            const uint32_t fb = ch ? f1 : f0;
            const uint32_t st = dsm + (uint32_t)ch * STG_SZ;
            mbar_arrive_tx(fb, 2 * TILEA_B);
            bulk_g2s(st,           aH + (size_t)ch * TILEA_B, TILEA_B, fb);
            bulk_g2s(st + OFF_ALO, aL + (size_t)ch * TILEA_B, TILEA_B, fb);
        }
        uint32_t phe[2] = {0, 0};
#pragma unroll 1
        for (int nx = 2; nx < 16; nx++) {
            const int s = nx & 1;
            mbar_wait(s ? e1 : e0, phe[s]); phe[s] ^= 1;
            const uint32_t fb = s ? f1 : f0;
            const uint32_t st = dsm + (uint32_t)s * STG_SZ;
            mbar_arrive_tx(fb, (uint32_t)STG_SZ);
            bulk_g2s(st,           aH + (size_t)nx * TILEA_B, TILEA_B, fb);
            bulk_g2s(st + OFF_ALO, aL + (size_t)nx * TILEA_B, TILEA_B, fb);
            bulk_g2s(st + OFF_BHI, bH + (size_t)nx * TILEB_B, TILEB_B, fb);
            bulk_g2s(st + OFF_BLO, bL + (size_t)nx * TILEB_B, TILEB_B, fb);
        }
    }

    // ---- consumer: MMA issue ----
    if (tid == 0) {
        uint32_t phf[2] = {0, 0};
#pragma unroll 1
        for (int ch = 0; ch < 16; ch++) {
            const int s = ch & 1;
            mbar_wait(s ? f1 : f0, phf[s]); phf[s] ^= 1;

            const uint32_t st = dsm + (uint32_t)s * STG_SZ;
            const uint64_t dah = mkdesc(st);
            const uint64_t dal = mkdesc(st + OFF_ALO);
            const uint64_t dbh = mkdesc(st + OFF_BHI);
            const uint64_t dbl = mkdesc(st + OFF_BLO);
#pragma unroll
            for (int ks = 0; ks < 4; ks++) {
                mma_f16_ss(tmem, dah + ks * 2, dbh + ks * 2, GEMM_IDESC,
                           (ch == 0 && ks == 0) ? 0u : 1u);
                mma_f16_ss(tmem, dah + ks * 2, dbl + ks * 2, GEMM_IDESC, 1u);
                mma_f16_ss(tmem, dal + ks * 2, dbh + ks * 2, GEMM_IDESC, 1u);
            }
            tc_commit(s ? e1 : e0);
        }
        tc_commit(db);
    }

    mbar_wait(db, 0);
    TC_FENCE_AFTER();

    // ---------------- fused epilogue: v = relu(step*(c - acc)) [*act] ----
    const int sp   = wid & 3;
    const int half = wid >> 2;
    const int lr   = sp * 32 + lane;
    const int r    = bm0 + lr;

#pragma unroll 1
    for (int cb = 0; cb < 128; cb += 32) {
        uint32_t dreg[32];
        LDTM_X32(dreg, tmem + half * 128 + cb);

        const int coff = half * 128 + cb;
        const int gch  = (bn0 + coff) >> 6;
        const int lc0  = coff & 63;
        const size_t tb = ((size_t)(blockIdx.y * 16 + gch)) * TILEA_B;
        const size_t blin = (size_t)r * Mm + bn0 + coff;

        float4   cv[8];
        float4   av[8];
        uint32_t boff[8];
#pragma unroll
        for (int g = 0; g < 8; g++) {
            const int j0 = g * 4;
            boff[g] = swz((uint32_t)(lr * 128 + (lc0 + j0) * 2));
            cv[g] = *(const float4*)&cc[blin + j0];
            if (masked) av[g] = *(const float4*)&act[blin + j0];
        }

        TC_WAIT_LD();

#pragma unroll
        for (int g = 0; g < 8; g++) {
            const int j0 = g * 4;
            const float* cvp = (const float*)&cv[g];
            const float* avp = (const float*)&av[g];
            uint16_t oh[4], ol[4];
#pragma unroll
            for (int k = 0; k < 4; k++) {
                float acc = __uint_as_float(dreg[j0 + k]);
                float v = fmaxf(STEPC * (cvp[k] - acc), 0.f);
                if (masked) v *= avp[k];
                uint16_t hb = f2bfbits(v);
                oh[k] = hb;
                ol[k] = f2bfbits(v - bfbits2f(hb));
            }
            *(uint64_t*)((char*)ohi + tb + boff[g]) =
                (uint64_t)oh[0] | ((uint64_t)oh[1] << 16)
                | ((uint64_t)oh[2] << 32) | ((uint64_t)oh[3] << 48);
            *(uint64_t*)((char*)olo + tb + boff[g]) =
                (uint64_t)ol[0] | ((uint64_t)ol[1] << 16)
                | ((uint64_t)ol[2] << 32) | ((uint64_t)ol[3] << 48);
        }
    }

    GDC_LAUNCH();

    __syncthreads();
    if (wid == 0) { TC_RELINQ(); TC_DEALLOC(tmem, 256); }
#endif  // HAS_TCGEN05
}

// epilogue variants (cg1 peripheral GEMMs)
enum { E_C = 0, E_ACT, E_MSK, E_Z, E_OUT, E_Q };

// ---------------------------------------------------------------------------
// Generic cg1 tcgen05 GEMM, fused epilogues, optional PDL early loads.
//   early bit0: A operand is pre-chain-safe; bit1: B operand pre-chain-safe
//   E_Q writes Q' = acc - (1/step) I as B-image.
// ---------------------------------------------------------------------------
template <int EPI>
__global__ void __launch_bounds__(256, 1) tc_gemm(
    const __nv_bfloat16* __restrict__ Ahi, const __nv_bfloat16* __restrict__ Alo,
    const __nv_bfloat16* __restrict__ Bhi, const __nv_bfloat16* __restrict__ Blo,
    int nch,
    const float* __restrict__ v1, const float* __restrict__ v2,
    float* __restrict__ o32,
    __nv_bfloat16* __restrict__ ohi, __nv_bfloat16* __restrict__ olo,
    int Ncols, int early)
{
#if HAS_TCGEN05
    extern __shared__ char draw[];
    const uint32_t dsm = (s2u(draw) + 1023u) & ~1023u;

    __shared__ uint32_t s_tmem;
    __shared__ __align__(8) uint64_t s_bar[5];

    const int tid  = threadIdx.x;
    const int wid  = tid >> 5;
    const int lane = tid & 31;
    const int bm0  = blockIdx.y * TM;
    const int bn0  = blockIdx.x * TN;

    const uint32_t f0 = s2u(&s_bar[0]);
    const uint32_t f1 = s2u(&s_bar[1]);
    const uint32_t e0 = s2u(&s_bar[2]);
    const uint32_t e1 = s2u(&s_bar[3]);
    const uint32_t db = s2u(&s_bar[4]);

    if (wid == 0) TC_ALLOC(s2u(&s_tmem), 256);
    if (tid == 0) {
        mbar_init(f0, 1); mbar_init(f1, 1);
        mbar_init(e0, 1); mbar_init(e1, 1);
        mbar_init(db, 1);
    }
    __syncthreads();
    uint32_t tmem;
    asm volatile("ld.shared.b32 %0, [%1];" : "=r"(tmem) : "r"(s2u(&s_tmem)));

    const int earlyA = early & 1, earlyB = early & 2;
    const char* aH = (const char*)Ahi + (size_t)blockIdx.y * nch * TILEA_B;
    const char* aL = (const char*)Alo + (size_t)blockIdx.y * nch * TILEA_B;
    const char* bH = (const char*)Bhi + (size_t)blockIdx.x * nch * TILEB_B;
    const char* bL = (const char*)Blo + (size_t)blockIdx.x * nch * TILEB_B;

    if (tid == 0 && earlyB) {
#pragma unroll
        for (int ch = 0; ch < 2; ch++) {
            const uint32_t fb = ch ? f1 : f0;
            const uint32_t st = dsm + (uint32_t)ch * STG_SZ;
            mbar_tx_only(fb, 2 * TILEB_B);
            bulk_g2s(st + OFF_BHI, bH + (size_t)ch * TILEB_B, TILEB_B, fb);
            bulk_g2s(st + OFF_BLO, bL + (size_t)ch * TILEB_B, TILEB_B, fb);
        }
    }
    if (tid == 0 && earlyA) {
#pragma unroll
        for (int ch = 0; ch < 2; ch++) {
            const uint32_t fb = ch ? f1 : f0;
            const uint32_t st = dsm + (uint32_t)ch * STG_SZ;
            mbar_arrive_tx(fb, earlyB ? 2 * TILEA_B : (uint32_t)STG_SZ);
            bulk_g2s(st,           aH + (size_t)ch * TILEA_B, TILEA_B, fb);
            bulk_g2s(st + OFF_ALO, aL + (size_t)ch * TILEA_B, TILEA_B, fb);
            if (!earlyB) {
                bulk_g2s(st + OFF_BHI, bH + (size_t)ch * TILEB_B, TILEB_B, fb);
                bulk_g2s(st + OFF_BLO, bL + (size_t)ch * TILEB_B, TILEB_B, fb);
            }
        }
    }
    if (!earlyA) {
        GDC_WAIT();
        if (tid == 0) {
#pragma unroll
            for (int ch = 0; ch < 2; ch++) {
                const uint32_t fb = ch ? f1 : f0;
                const uint32_t st = dsm + (uint32_t)ch * STG_SZ;
                mbar_arrive_tx(fb, earlyB ? 2 * TILEA_B : (uint32_t)STG_SZ);
                bulk_g2s(st,           aH + (size_t)ch * TILEA_B, TILEA_B, fb);
                bulk_g2s(st + OFF_ALO, aL + (size_t)ch * TILEA_B, TILEA_B, fb);
                if (!earlyB) {
                    bulk_g2s(st + OFF_BHI, bH + (size_t)ch * TILEB_B, TILEB_B, fb);
                    bulk_g2s(st + OFF_BLO, bL + (size_t)ch * TILEB_B, TILEB_B, fb);
                }
            }
        }
    }

    if (tid == 0) {
        uint32_t phf[2] = {0, 0}, phe[2] = {0, 0};
#pragma unroll 1
        for (int ch = 0; ch < nch; ch++) {
            const int s = ch & 1;
            mbar_wait(s ? f1 : f0, phf[s]); phf[s] ^= 1;

            const uint32_t st = dsm + (uint32_t)s * STG_SZ;
            const uint64_t dah = mkdesc(st);
            const uint64_t dal = mkdesc(st + OFF_ALO);
            const uint64_t dbh = mkdesc(st + OFF_BHI);
            const uint64_t dbl = mkdesc(st + OFF_BLO);
#pragma unroll
            for (int ks = 0; ks < 4; ks++) {
                mma_f16_ss(tmem, dah + ks * 2, dbh + ks * 2, GEMM_IDESC,
                           (ch == 0 && ks == 0) ? 0u : 1u);
                mma_f16_ss(tmem, dah + ks * 2, dbl + ks * 2, GEMM_IDESC, 1u);
                mma_f16_ss(tmem, dal + ks * 2, dbh + ks * 2, GEMM_IDESC, 1u);
            }
            tc_commit(s ? e1 : e0);

            if (ch + 2 < nch) {
                mbar_wait(s ? e1 : e0, phe[s]); phe[s] ^= 1;
                const int nx = ch + 2;
                const uint32_t fb = s ? f1 : f0;
                const uint32_t st2 = dsm + (uint32_t)s * STG_SZ;
                mbar_arrive_tx(fb, (uint32_t)STG_SZ);
                bulk_g2s(st2,           aH + (size_t)nx * TILEA_B, TILEA_B, fb);
                bulk_g2s(st2 + OFF_ALO, aL + (size_t)nx * TILEA_B, TILEA_B, fb);
                bulk_g2s(st2 + OFF_BHI, bH + (size_t)nx * TILEB_B, TILEB_B, fb);
                bulk_g2s(st2 + OFF_BLO, bL + (size_t)nx * TILEB_B, TILEB_B, fb);
            }
        }
        tc_commit(db);
    }

    mbar_wait(db, 0);
    if (earlyA) GDC_WAIT();   // chain ordering before epilogue reads (e.g. act)
    TC_FENCE_AFTER();

    const int sp   = wid & 3;
    const int half = wid >> 2;
    const int lr   = sp * 32 + lane;
    const int r    = bm0 + lr;
    const int nchO = Ncols >> 6;

#pragma unroll 1
    for (int cb = 0; cb < 128; cb += 32) {
        uint32_t dreg[32];
        LDTM_X32(dreg, tmem + half * 128 + cb);
        TC_WAIT_LD();

        const int coff = half * 128 + cb;
        const int gch  = (bn0 + coff) >> 6;
        const int lc0  = coff & 63;
        const size_t blin = (size_t)r * Ncols + bn0 + coff;
        const size_t tbA = ((size_t)(blockIdx.y * nchO + gch)) * TILEA_B;
        const size_t tbB = ((size_t)((r >> 8) * nchO + gch)) * TILEB_B;
        const int brow = r & 255;

#pragma unroll
        for (int j0 = 0; j0 < 32; j0 += 4) {
            const uint32_t boffA = swz((uint32_t)(lr * 128 + (lc0 + j0) * 2));
            float res[4];
#pragma unroll
            for (int k = 0; k < 4; k++) res[k] = __uint_as_float(dreg[j0 + k]);

            if (EPI == E_C) {
                float4 bv = *(const float4*)&v1[bn0 + coff + j0];
                const float* bp = (const float*)&bv;
                uint16_t oh[4], ol[4];
                float cvv[4];
#pragma unroll
                for (int k = 0; k < 4; k++) {
                    float cv = res[k] - bp[k];
                    cvv[k] = cv;
                    float v = fmaxf(STEPC * cv, 0.f);
                    uint16_t hb = f2bfbits(v);
                    oh[k] = hb; ol[k] = f2bfbits(v - bfbits2f(hb));
                }
                *(float4*)&o32[blin + j0] = make_float4(cvv[0], cvv[1], cvv[2], cvv[3]);
                *(uint64_t*)((char*)ohi + tbA + boffA) =
                    (uint64_t)oh[0] | ((uint64_t)oh[1] << 16)
                    | ((uint64_t)oh[2] << 32) | ((uint64_t)oh[3] << 48);
                *(uint64_t*)((char*)olo + tbA + boffA) =
                    (uint64_t)ol[0] | ((uint64_t)ol[1] << 16)
                    | ((uint64_t)ol[2] << 32) | ((uint64_t)ol[3] << 48);
            } else if (EPI == E_ACT) {
                float4 bv = *(const float4*)&v1[bn0 + coff + j0];
                const float* bp = (const float*)&bv;
                float o[4];
#pragma unroll
                for (int k = 0; k < 4; k++)
                    o[k] = (res[k] >= bp[k] - TOLV) ? 1.f : 0.f;
                *(float4*)&o32[blin + j0] = make_float4(o[0], o[1], o[2], o[3]);
            } else if (EPI == E_MSK) {
                float4 avv = *(const float4*)&v1[blin + j0];
                const float* ap = (const float*)&avv;
                uint16_t oh[4], ol[4];
                float mm[4];
#pragma unroll
                for (int k = 0; k < 4; k++) {
                    float m = res[k] * ap[k];
                    mm[k] = m;
                    float v = fmaxf(STEPC * m, 0.f) * ap[k];
                    uint16_t hb = f2bfbits(v);
                    oh[k] = hb; ol[k] = f2bfbits(v - bfbits2f(hb));
                }
                *(float4*)&o32[blin + j0] = make_float4(mm[0], mm[1], mm[2], mm[3]);
                *(uint64_t*)((char*)ohi + tbA + boffA) =
                    (uint64_t)oh[0] | ((uint64_t)oh[1] << 16)
                    | ((uint64_t)oh[2] << 32) | ((uint64_t)oh[3] << 48);
                *(uint64_t*)((char*)olo + tbA + boffA) =
                    (uint64_t)ol[0] | ((uint64_t)ol[1] << 16)
                    | ((uint64_t)ol[2] << 32) | ((uint64_t)ol[3] << 48);
            } else if (EPI == E_Z) {
                float4 xv = *(const float4*)&v1[blin + j0];
                float4 uv = *(const float4*)&v2[blin + j0];
                const float* xp = (const float*)&xv;
                const float* up = (const float*)&uv;
                uint16_t oh[4], ol[4];
#pragma unroll
                for (int k = 0; k < 4; k++) {
                    float zv = xp[k] + up[k] - res[k];
                    uint16_t hb = f2bfbits(zv);
                    oh[k] = hb; ol[k] = f2bfbits(zv - bfbits2f(hb));
                }
                *(uint64_t*)((char*)ohi + tbA + boffA) =
                    (uint64_t)oh[0] | ((uint64_t)oh[1] << 16)
                    | ((uint64_t)oh[2] << 32) | ((uint64_t)oh[3] << 48);
                *(uint64_t*)((char*)olo + tbA + boffA) =
                    (uint64_t)ol[0] | ((uint64_t)ol[1] << 16)
                    | ((uint64_t)ol[2] << 32) | ((uint64_t)ol[3] << 48);
            } else if (EPI == E_OUT) {
                float4 uv = *(const float4*)&v1[blin + j0];
                const float* up = (const float*)&uv;
                float o[4];
#pragma unroll
                for (int k = 0; k < 4; k++) o[k] = up[k] - res[k];
                *(float4*)&o32[blin + j0] = make_float4(o[0], o[1], o[2], o[3]);
            } else if (EPI == E_Q) {
                const uint32_t boffB = swz((uint32_t)(brow * 128 + (lc0 + j0) * 2));
                uint16_t oh[4], ol[4];
#pragma unroll
                for (int k = 0; k < 4; k++) {
                    float qv = res[k];
                    if (r == bn0 + coff + j0 + k) qv -= INVSTEP;   // Q' = Q - (1/step) I
                    uint16_t hb = f2bfbits(qv);
                    oh[k] = hb; ol[k] = f2bfbits(qv - bfbits2f(hb));
                }
                *(uint64_t*)((char*)ohi + tbB + boffB) =
                    (uint64_t)oh[0] | ((uint64_t)oh[1] << 16)
                    | ((uint64_t)oh[2] << 32) | ((uint64_t)oh[3] << 48);
                *(uint64_t*)((char*)olo + tbB + boffB) =
                    (uint64_t)ol[0] | ((uint64_t)ol[1] << 16)
                    | ((uint64_t)ol[2] << 32) | ((uint64_t)ol[3] << 48);
            }
        }
    }

    GDC_LAUNCH();

    __syncthreads();
    if (wid == 0) { TC_RELINQ(); TC_DEALLOC(tmem, 256); }
#endif  // HAS_TCGEN05
}

// ---------------- prep kernels ----------------
__device__ __forceinline__ void img_store(__nv_bfloat16* hi, __nv_bfloat16* lo,
                                          size_t tb, uint32_t boff, float v)
{
    __nv_bfloat16 h = __float2bfloat16(v);
    *(__nv_bfloat16*)((char*)hi + tb + boff) = h;
    *(__nv_bfloat16*)((char*)lo + tb + boff) = __float2bfloat16(v - __bfloat162float(h));
}

__global__ void split_A_images(const float* __restrict__ A)
{
    int i = blockIdx.x * blockDim.x + threadIdx.x;
    if (i >= Mm * Nn) return;
    int r = i >> 9, k = i & 511;
    float v = A[i];
    int ch = k >> 6, lc = k & 63;
    {
        int bm = r >> 7, lrow = r & 127;
        size_t tb = ((size_t)(bm * 8 + ch)) * TILEA_B;
        img_store(g_AAi_h, g_AAi_l, tb, swz((uint32_t)(lrow * 128 + lc * 2)), v);
    }
    {
        int nb = r >> 8, brow = r & 255;
        size_t tb = ((size_t)(nb * 8 + ch)) * TILEB_B;
        img_store(g_ABi_h, g_ABi_l, tb, swz((uint32_t)(brow * 128 + lc * 2)), v);
    }
}

__global__ void split_AT_image(const float* __restrict__ A)
{
    int i = blockIdx.x * blockDim.x + threadIdx.x;
    if (i >= Nn * Mm) return;
    int n = i >> 10, k = i & 1023;
    float v = A[(size_t)k * Nn + n];
    int nb = n >> 8, brow = n & 255, ch = k >> 6, lc = k & 63;
    size_t tb = ((size_t)(nb * 16 + ch)) * TILEB_B;
    img_store(g_ATi_h, g_ATi_l, tb, swz((uint32_t)(brow * 128 + lc * 2)), v);
}

__global__ void split_xu_u(const float* __restrict__ x, const float* __restrict__ u)
{
    int i = blockIdx.x * blockDim.x + threadIdx.x;
    if (i >= Bsz * Nn) return;
    int r = i >> 9, k = i & 511;
    int bm = r >> 7, lrow = r & 127, ch = k >> 6, lc = k & 63;
    size_t tb = ((size_t)(bm * 8 + ch)) * TILEA_B;
    uint32_t boff = swz((uint32_t)(lrow * 128 + lc * 2));
    float uv = u[i];
    img_store(g_xu_h, g_xu_l, tb, boff, x[i] + uv);
    img_store(g_u_h,  g_u_l,  tb, boff, uv);
}

// ---------------------------------------------------------------------------
extern "C" void kernel_launch(void* const* d_in, const int* in_sizes, int n_in,
                              void* d_out, int out_size)
{
    const float* x = (const float*)d_in[0];
    const float* u = (const float*)d_in[1];
    const float* A = (const float*)d_in[2];
    const float* b = (const float*)d_in[3];
    float* out = (float*)d_out;

    float *c, *msk, *act;
    __nv_bfloat16 *AAh, *AAl, *ABh, *ABl, *ATh, *ATl, *XUh, *XUl, *Uh, *Ul,
                  *Zh, *Zl, *Qh, *Ql, *lAh, *lAl, *lBh, *lBl;
    cudaGetSymbolAddress((void**)&c,   g_c);
    cudaGetSymbolAddress((void**)&msk, g_msk);
    cudaGetSymbolAddress((void**)&act, g_act);
    cudaGetSymbolAddress((void**)&AAh, g_AAi_h); cudaGetSymbolAddress((void**)&AAl, g_AAi_l);
    cudaGetSymbolAddress((void**)&ABh, g_ABi_h); cudaGetSymbolAddress((void**)&ABl, g_ABi_l);
    cudaGetSymbolAddress((void**)&ATh, g_ATi_h); cudaGetSymbolAddress((void**)&ATl, g_ATi_l);
    cudaGetSymbolAddress((void**)&XUh, g_xu_h);  cudaGetSymbolAddress((void**)&XUl, g_xu_l);
    cudaGetSymbolAddress((void**)&Uh,  g_u_h);   cudaGetSymbolAddress((void**)&Ul,  g_u_l);
    cudaGetSymbolAddress((void**)&Zh,  g_z_h);   cudaGetSymbolAddress((void**)&Zl,  g_z_l);
    cudaGetSymbolAddress((void**)&Qh,  g_Qhi);   cudaGetSymbolAddress((void**)&Ql,  g_Qlo);
    cudaGetSymbolAddress((void**)&lAh, g_lAhi);  cudaGetSymbolAddress((void**)&lAl, g_lAlo);
    cudaGetSymbolAddress((void**)&lBh, g_lBhi);  cudaGetSymbolAddress((void**)&lBl, g_lBlo);

    cudaFuncSetAttribute(tc_gemm<E_C>,   cudaFuncAttributeMaxDynamicSharedMemorySize, DSMEM);
    cudaFuncSetAttribute(tc_gemm<E_ACT>, cudaFuncAttributeMaxDynamicSharedMemorySize, DSMEM);
    cudaFuncSetAttribute(tc_gemm<E_MSK>, cudaFuncAttributeMaxDynamicSharedMemorySize, DSMEM);
    cudaFuncSetAttribute(tc_gemm<E_Z>,   cudaFuncAttributeMaxDynamicSharedMemorySize, DSMEM);
    cudaFuncSetAttribute(tc_gemm<E_OUT>, cudaFuncAttributeMaxDynamicSharedMemorySize, DSMEM);
    cudaFuncSetAttribute(tc_gemm<E_Q>,   cudaFuncAttributeMaxDynamicSharedMemorySize, DSMEM);
    cudaFuncSetAttribute(pgd_pdl,        cudaFuncAttributeMaxDynamicSharedMemorySize, DSMEM);

    const dim3 blk(256);
    const int EW = 256;

    // prep (plain launches — first in chain)
    split_A_images<<<(Mm * Nn + EW - 1) / EW, EW>>>(A);
    split_AT_image<<<(Nn * Mm + EW - 1) / EW, EW>>>(A);
    split_xu_u<<<(int)(((size_t)Bsz * Nn + EW - 1) / EW), EW>>>(x, u);

    // PDL config (grid mutated per launch)
    cudaLaunchAttribute pdlAttr;
    pdlAttr.id = cudaLaunchAttributeProgrammaticStreamSerialization;
    pdlAttr.val.programmaticStreamSerializationAllowed = 1;
    cudaLaunchConfig_t cfg = {};
    cfg.blockDim = blk;
    cfg.dynamicSmemBytes = DSMEM;
    cfg.stream = 0;
    cfg.attrs = &pdlAttr;
    cfg.numAttrs = 1;

    // Q' = A @ A^T - (1/step) I -> Q B-images
    cfg.gridDim = dim3(4, 8);
    cudaLaunchKernelEx(&cfg, tc_gemm<E_Q>,
                       (const __nv_bfloat16*)AAh, (const __nv_bfloat16*)AAl,
                       (const __nv_bfloat16*)ABh, (const __nv_bfloat16*)ABl, 8,
                       (const float*)nullptr, (const float*)nullptr,
                       (float*)nullptr, Qh, Ql, 1024, 0);

    // c = xu @ A^T - b (+ lam init): operands from prep -> early=3
    cfg.gridDim = dim3(4, 32);
    cudaLaunchKernelEx(&cfg, tc_gemm<E_C>,
                       (const __nv_bfloat16*)XUh, (const __nv_bfloat16*)XUl,
                       (const __nv_bfloat16*)ABh, (const __nv_bfloat16*)ABl, 8,
                       (const float*)b, (const float*)nullptr,
                       c, lAh, lAl, 1024, 3);

    // PGD iters 2..50 (49 PDL launches, folded Q')
    cfg.gridDim = dim3(4, 32);
    __nv_bfloat16 *curh = lAh, *curl = lAl, *nxth = lBh, *nxtl = lBl;
    for (int it = 1; it < 50; it++) {
        cudaLaunchKernelEx(&cfg, pgd_pdl,
                           (const __nv_bfloat16*)curh, (const __nv_bfloat16*)curl,
                           (const __nv_bfloat16*)Qh,  (const __nv_bfloat16*)Ql,
                           (const float*)c, (const float*)nullptr,
                           nxth, nxtl, 0);
        __nv_bfloat16* t;
        t = curh; curh = nxth; nxth = t;
        t = curl; curl = nxtl; nxtl = t;
    }

    // z = x + u - lam @ A  (A = lam from pred -> earlyB only)
    cfg.gridDim = dim3(2, 32);
    cudaLaunchKernelEx(&cfg, tc_gemm<E_Z>,
                       (const __nv_bfloat16*)curh, (const __nv_bfloat16*)curl,
                       (const __nv_bfloat16*)ATh, (const __nv_bfloat16*)ATl, 16,
                       (const float*)x, (const float*)u,
                       (float*)nullptr, Zh, Zl, 512, 2);
    // active  (A = z from pred -> earlyB only)
    cfg.gridDim = dim3(4, 32);
    cudaLaunchKernelEx(&cfg, tc_gemm<E_ACT>,
                       (const __nv_bfloat16*)Zh, (const __nv_bfloat16*)Zl,
                       (const __nv_bfloat16*)ABh, (const __nv_bfloat16*)ABl, 8,
                       (const float*)b, (const float*)nullptr,
                       act, (__nv_bfloat16*)nullptr, (__nv_bfloat16*)nullptr, 1024, 2);
    // masked (+ masked lam init): both operands prep-constant -> early=3
    cfg.gridDim = dim3(4, 32);
    cudaLaunchKernelEx(&cfg, tc_gemm<E_MSK>,
                       (const __nv_bfloat16*)Uh, (const __nv_bfloat16*)Ul,
                       (const __nv_bfloat16*)ABh, (const __nv_bfloat16*)ABl, 8,
                       (const float*)act, (const float*)nullptr,
                       msk, lAh, lAl, 1024, 3);

    // masked PGD iters 2..10 (9 PDL launches, folded Q')
    cfg.gridDim = dim3(4, 32);
    curh = lAh; curl = lAl; nxth = lBh; nxtl = lBl;
    for (int it = 1; it < 10; it++) {
        cudaLaunchKernelEx(&cfg, pgd_pdl,
                           (const __nv_bfloat16*)curh, (const __nv_bfloat16*)curl,
                           (const __nv_bfloat16*)Qh,  (const __nv_bfloat16*)Ql,
                           (const float*)msk, (const float*)act,
                           nxth, nxtl, 1);
        __nv_bfloat16* t;
        t = curh; curh = nxth; nxth = t;
        t = curl; curl = nxtl; nxtl = t;
    }

    // out = u - lam @ A  (A = lam from pred -> earlyB only)
    cfg.gridDim = dim3(2, 32);
    cudaLaunchKernelEx(&cfg, tc_gemm<E_OUT>,
                       (const __nv_bfloat16*)curh, (const __nv_bfloat16*)curl,
                       (const __nv_bfloat16*)ATh, (const __nv_bfloat16*)ATl, 16,
                       (const float*)u, (const float*)nullptr,
                       out, (__nv_bfloat16*)nullptr, (__nv_bfloat16*)nullptr, 512, 2);
}

// round 14
// speedup vs baseline: 2.3900x; 1.0439x over previous
#include <cuda_runtime.h>
#include <cuda_bf16.h>
#include <cstddef>
#include <cstdint>

// Problem constants (B=4096, n=512, m=1024)
#define Bsz 4096
#define Nn  512
#define Mm  1024
#define STEPC 0.01f
#define INVSTEP 100.0f
#define TOLV 1e-5f

// ---- tensor tile config ----
#define TM 128
#define TN 256
#define KC 64
#define TILEA_B 16384          // 128x64 bf16 tile bytes
#define TILEB_B 32768          // 256x64 bf16 tile bytes
// generic tc_gemm stage (3-operand): A hi/lo + B hi/lo
#define OFF_ALO 16384
#define OFF_BHI 32768
#define OFF_BLO 65536
#define STG_SZ  98304          // 96 KB per stage
#define DSMEM   (2 * STG_SZ + 1024)
// pgd stage (2-product): A hi + B hi/lo only
#define OFF2_BHI 16384
#define OFF2_BLO 49152
#define STG2_SZ  81920         // 80 KB per stage
#define DSMEM2   (2 * STG2_SZ + 1024)

#if defined(__CUDA_ARCH__) && defined(__CUDA_ARCH_FEAT_SM103_ALL)
#define HAS_TCGEN05 1
#else
#define HAS_TCGEN05 0
#endif

// ---------------- device scratch (allocation-free) ----------------
__device__ __align__(128) float g_c[(size_t)Bsz * Mm];
__device__ __align__(128) float g_msk[(size_t)Bsz * Mm];
__device__ __align__(128) float g_act[(size_t)Bsz * Mm];
__device__ __align__(128) float g_qdiag[Mm];                // diag(Q') fp32
__device__ __align__(128) __nv_bfloat16 g_AAi_h[Mm * Nn];   // A as A-image [8][8]
__device__ __align__(128) __nv_bfloat16 g_AAi_l[Mm * Nn];
__device__ __align__(128) __nv_bfloat16 g_ABi_h[Mm * Nn];   // A as B-image [4][8]
__device__ __align__(128) __nv_bfloat16 g_ABi_l[Mm * Nn];
__device__ __align__(128) __nv_bfloat16 g_ATi_h[Nn * Mm];   // A^T as B-image [2][16]
__device__ __align__(128) __nv_bfloat16 g_ATi_l[Nn * Mm];
__device__ __align__(128) __nv_bfloat16 g_xu_h[(size_t)Bsz * Nn];
__device__ __align__(128) __nv_bfloat16 g_xu_l[(size_t)Bsz * Nn];
__device__ __align__(128) __nv_bfloat16 g_u_h[(size_t)Bsz * Nn];
__device__ __align__(128) __nv_bfloat16 g_u_l[(size_t)Bsz * Nn];
__device__ __align__(128) __nv_bfloat16 g_z_h[(size_t)Bsz * Nn];
__device__ __align__(128) __nv_bfloat16 g_z_l[(size_t)Bsz * Nn];
// Q' = Q - (1/step) I as B-image [4 nb][16 ch][256x64, 32 KB]
__device__ __align__(128) __nv_bfloat16 g_Qhi[Mm * Mm];
__device__ __align__(128) __nv_bfloat16 g_Qlo[Mm * Mm];
__device__ __align__(128) __nv_bfloat16 g_lAhi[(size_t)Bsz * Mm]; // lam A-images [32][16]
__device__ __align__(128) __nv_bfloat16 g_lAlo[(size_t)Bsz * Mm];
__device__ __align__(128) __nv_bfloat16 g_lBhi[(size_t)Bsz * Mm];
__device__ __align__(128) __nv_bfloat16 g_lBlo[(size_t)Bsz * Mm];

// ---------------- helpers ----------------
__device__ __forceinline__ uint32_t s2u(const void* p) {
    uint32_t a;
    asm("{ .reg .u64 t; cvta.to.shared.u64 t, %1; cvt.u32.u64 %0, t; }"
        : "=r"(a) : "l"(p));
    return a;
}
__device__ __forceinline__ uint32_t swz(uint32_t off) {
    return off ^ ((off >> 3) & 0x70);
}
__device__ __forceinline__ void mbar_init(uint32_t a, uint32_t cnt) {
    asm volatile("mbarrier.init.shared.b64 [%0], %1;" :: "r"(a), "r"(cnt) : "memory");
}
__device__ __forceinline__ void mbar_arrive_tx(uint32_t a, uint32_t bytes) {
    asm volatile("mbarrier.arrive.expect_tx.shared.b64 _, [%0], %1;"
                 :: "r"(a), "r"(bytes) : "memory");
}
__device__ __forceinline__ void mbar_tx_only(uint32_t a, uint32_t bytes) {
    asm volatile("mbarrier.expect_tx.shared.b64 [%0], %1;"
                 :: "r"(a), "r"(bytes) : "memory");
}
__device__ __forceinline__ void mbar_wait(uint32_t a, uint32_t phase) {
    uint32_t done = 0;
    while (!done) {
        asm volatile(
            "{ .reg .pred p; mbarrier.try_wait.parity.shared.b64 p, [%1], %2; "
            "selp.b32 %0, 1, 0, p; }"
            : "=r"(done) : "r"(a), "r"(phase) : "memory");
    }
}
__device__ __forceinline__ void bulk_g2s(uint32_t dst, const void* src,
                                         uint32_t bytes, uint32_t mbar) {
    asm volatile(
        "cp.async.bulk.shared::cluster.global.mbarrier::complete_tx::bytes "
        "[%0], [%1], %2, [%3];"
        :: "r"(dst), "l"(src), "r"(bytes), "r"(mbar) : "memory");
}
__device__ __forceinline__ uint64_t mkdesc(uint32_t addr) {
    return ((uint64_t)2 << 61) | ((uint64_t)1 << 46) | ((uint64_t)64 << 32)
         | ((uint64_t)1 << 16) | ((addr >> 4) & 0x3FFF);
}
#define GEMM_IDESC ((1u<<4) | (1u<<7) | (1u<<10) | ((TN/8)<<17) | ((128/16)<<24))
#define GDC_WAIT()   asm volatile("griddepcontrol.wait;" ::: "memory")
#define GDC_LAUNCH() asm volatile("griddepcontrol.launch_dependents;" ::: "memory")

__device__ __forceinline__ float bfbits2f(uint16_t u) {
    __nv_bfloat16_raw r; r.x = u;
    return __bfloat162float(__nv_bfloat16(r));
}
__device__ __forceinline__ uint16_t f2bfbits(float f) {
    __nv_bfloat16 h = __float2bfloat16(f);
    __nv_bfloat16_raw r = (__nv_bfloat16_raw)h;
    return r.x;
}

#if HAS_TCGEN05
__device__ __forceinline__ void mma_f16_ss(uint32_t d, uint64_t a, uint64_t b,
                                           uint32_t idesc, uint32_t en) {
    asm volatile(
        "{\n\t.reg .pred p;\n\tsetp.ne.u32 p, %5, 0;\n\t"
        "tcgen05.mma.cta_group::1.kind::f16 [%0], %1, %2, %3, {%4,%4,%4,%4}, p;\n\t}"
        :: "r"(d), "l"(a), "l"(b), "r"(idesc), "r"(0u), "r"(en) : "memory");
}
__device__ __forceinline__ void tc_commit(uint32_t mbar) {
    asm volatile(
        "tcgen05.commit.cta_group::1.mbarrier::arrive::one.shared::cluster.b64 [%0];"
        :: "r"(mbar) : "memory");
}
#define TC_ALLOC(sres, n) \
    asm volatile("tcgen05.alloc.cta_group::1.sync.aligned.shared::cta.b32 [%0], %1;" \
                 :: "r"(sres), "r"((uint32_t)(n)) : "memory")
#define TC_RELINQ() \
    asm volatile("tcgen05.relinquish_alloc_permit.cta_group::1.sync.aligned;")
#define TC_DEALLOC(t, n) \
    asm volatile("tcgen05.dealloc.cta_group::1.sync.aligned.b32 %0, %1;" :: "r"(t), "r"((uint32_t)(n)))
#define TC_FENCE_AFTER()  asm volatile("tcgen05.fence::after_thread_sync;" ::: "memory")
#define TC_WAIT_LD()      asm volatile("tcgen05.wait::ld.sync.aligned;" ::: "memory")
#define LDTM_X32(r, a) \
    asm volatile( \
        "tcgen05.ld.sync.aligned.32x32b.x32.b32 " \
        "{%0,%1,%2,%3,%4,%5,%6,%7,%8,%9,%10,%11,%12,%13,%14,%15," \
        "%16,%17,%18,%19,%20,%21,%22,%23,%24,%25,%26,%27,%28,%29,%30,%31}, [%32];" \
        : "=r"((r)[0]),"=r"((r)[1]),"=r"((r)[2]),"=r"((r)[3]), \
          "=r"((r)[4]),"=r"((r)[5]),"=r"((r)[6]),"=r"((r)[7]), \
          "=r"((r)[8]),"=r"((r)[9]),"=r"((r)[10]),"=r"((r)[11]), \
          "=r"((r)[12]),"=r"((r)[13]),"=r"((r)[14]),"=r"((r)[15]), \
          "=r"((r)[16]),"=r"((r)[17]),"=r"((r)[18]),"=r"((r)[19]), \
          "=r"((r)[20]),"=r"((r)[21]),"=r"((r)[22]),"=r"((r)[23]), \
          "=r"((r)[24]),"=r"((r)[25]),"=r"((r)[26]),"=r"((r)[27]), \
          "=r"((r)[28]),"=r"((r)[29]),"=r"((r)[30]),"=r"((r)[31]) \
        : "r"(a))
#endif  // HAS_TCGEN05

// ---------------------------------------------------------------------------
// PGD iteration, folded Q' + 2-product MMA + diagonal compensation:
//   acc2 = lam_hi @ (Q'hi + Q'lo)      (2 tcgen05 products)
//   acc  = acc2 + lam_lo[r,c] * qd[c]  (diag of dropped lam_lo @ Q' product)
//   lam_new = relu(step * (c - acc))   [* act]
//   PDL + warp-specialized producer (tid 32) / consumer (tid 0).
// ---------------------------------------------------------------------------
__global__ void __launch_bounds__(256, 1) pgd_pdl(
    const __nv_bfloat16* __restrict__ Ahi, const __nv_bfloat16* __restrict__ Alo,
    const __nv_bfloat16* __restrict__ Bhi, const __nv_bfloat16* __restrict__ Blo,
    const float* __restrict__ cc, const float* __restrict__ act,
    const float* __restrict__ qd,
    __nv_bfloat16* __restrict__ ohi, __nv_bfloat16* __restrict__ olo,
    int masked)
{
#if HAS_TCGEN05
    extern __shared__ char draw[];
    const uint32_t dsm = (s2u(draw) + 1023u) & ~1023u;

    __shared__ uint32_t s_tmem;
    __shared__ __align__(8) uint64_t s_bar[5];

    const int tid  = threadIdx.x;
    const int wid  = tid >> 5;
    const int lane = tid & 31;
    const int bm0  = blockIdx.y * TM;
    const int bn0  = blockIdx.x * TN;

    const uint32_t f0 = s2u(&s_bar[0]);
    const uint32_t f1 = s2u(&s_bar[1]);
    const uint32_t e0 = s2u(&s_bar[2]);
    const uint32_t e1 = s2u(&s_bar[3]);
    const uint32_t db = s2u(&s_bar[4]);

    if (wid == 0) TC_ALLOC(s2u(&s_tmem), 256);
    if (tid == 0) {
        mbar_init(f0, 1); mbar_init(f1, 1);
        mbar_init(e0, 1); mbar_init(e1, 1);
        mbar_init(db, 1);
    }
    __syncthreads();
    uint32_t tmem;
    asm volatile("ld.shared.b32 %0, [%1];" : "=r"(tmem) : "r"(s2u(&s_tmem)));

    const char* aH = (const char*)Ahi + (size_t)blockIdx.y * 16 * TILEA_B;
    const char* bH = (const char*)Bhi + (size_t)blockIdx.x * 16 * TILEB_B;
    const char* bL = (const char*)Blo + (size_t)blockIdx.x * 16 * TILEB_B;

    // ---- producer: early Q loads (pre-wait; Q' is iteration-invariant) ----
    if (tid == 32) {
#pragma unroll
        for (int ch = 0; ch < 2; ch++) {
            const uint32_t fb = ch ? f1 : f0;
            const uint32_t st = dsm + (uint32_t)ch * STG2_SZ;
            mbar_tx_only(fb, 2 * TILEB_B);
            bulk_g2s(st + OFF2_BHI, bH + (size_t)ch * TILEB_B, TILEB_B, fb);
            bulk_g2s(st + OFF2_BLO, bL + (size_t)ch * TILEB_B, TILEB_B, fb);
        }
    }

    // all threads: wait for predecessor's lam/c/act writes
    GDC_WAIT();

    // ---- producer: lam_hi loads for stages 0,1 then stage refills ----
    if (tid == 32) {
#pragma unroll
        for (int ch = 0; ch < 2; ch++) {
            const uint32_t fb = ch ? f1 : f0;
            const uint32_t st = dsm + (uint32_t)ch * STG2_SZ;
            mbar_arrive_tx(fb, (uint32_t)TILEA_B);
            bulk_g2s(st, aH + (size_t)ch * TILEA_B, TILEA_B, fb);
        }
        uint32_t phe[2] = {0, 0};
#pragma unroll 1
        for (int nx = 2; nx < 16; nx++) {
            const int s = nx & 1;
            mbar_wait(s ? e1 : e0, phe[s]); phe[s] ^= 1;
            const uint32_t fb = s ? f1 : f0;
            const uint32_t st = dsm + (uint32_t)s * STG2_SZ;
            mbar_arrive_tx(fb, (uint32_t)STG2_SZ);
            bulk_g2s(st,            aH + (size_t)nx * TILEA_B, TILEA_B, fb);
            bulk_g2s(st + OFF2_BHI, bH + (size_t)nx * TILEB_B, TILEB_B, fb);
            bulk_g2s(st + OFF2_BLO, bL + (size_t)nx * TILEB_B, TILEB_B, fb);
        }
    }

    // ---- consumer: MMA issue (2 products per k-step) ----
    if (tid == 0) {
        uint32_t phf[2] = {0, 0};
#pragma unroll 1
        for (int ch = 0; ch < 16; ch++) {
            const int s = ch & 1;
            mbar_wait(s ? f1 : f0, phf[s]); phf[s] ^= 1;

            const uint32_t st = dsm + (uint32_t)s * STG2_SZ;
            const uint64_t dah = mkdesc(st);
            const uint64_t dbh = mkdesc(st + OFF2_BHI);
            const uint64_t dbl = mkdesc(st + OFF2_BLO);
#pragma unroll
            for (int ks = 0; ks < 4; ks++) {
                mma_f16_ss(tmem, dah + ks * 2, dbh + ks * 2, GEMM_IDESC,
                           (ch == 0 && ks == 0) ? 0u : 1u);
                mma_f16_ss(tmem, dah + ks * 2, dbl + ks * 2, GEMM_IDESC, 1u);
            }
            tc_commit(s ? e1 : e0);
        }
        tc_commit(db);
    }

    mbar_wait(db, 0);
    TC_FENCE_AFTER();

    // ---- fused epilogue: v = relu(step*(c - acc2 - lam_lo*qd)) [*act] ----
    const int sp   = wid & 3;
    const int half = wid >> 2;
    const int lr   = sp * 32 + lane;
    const int r    = bm0 + lr;

#pragma unroll 1
    for (int cb = 0; cb < 128; cb += 32) {
        uint32_t dreg[32];
        LDTM_X32(dreg, tmem + half * 128 + cb);

        const int coff = half * 128 + cb;
        const int gch  = (bn0 + coff) >> 6;
        const int lc0  = coff & 63;
        const size_t tb = ((size_t)(blockIdx.y * 16 + gch)) * TILEA_B;
        const size_t blin = (size_t)r * Mm + bn0 + coff;

        float4   cv[8];
        float4   qv[8];
        uint64_t l4[8];
        float4   av[8];
        uint32_t boff[8];
#pragma unroll
        for (int g = 0; g < 8; g++) {
            const int j0 = g * 4;
            boff[g] = swz((uint32_t)(lr * 128 + (lc0 + j0) * 2));
            cv[g] = *(const float4*)&cc[blin + j0];
            qv[g] = *(const float4*)&qd[bn0 + coff + j0];
            l4[g] = *(const uint64_t*)((const char*)Alo + tb + boff[g]);
            if (masked) av[g] = *(const float4*)&act[blin + j0];
        }

        TC_WAIT_LD();

#pragma unroll
        for (int g = 0; g < 8; g++) {
            const int j0 = g * 4;
            const float* cvp = (const float*)&cv[g];
            const float* qvp = (const float*)&qv[g];
            const float* avp = (const float*)&av[g];
            uint16_t oh[4], ol[4];
#pragma unroll
            for (int k = 0; k < 4; k++) {
                float acc = __uint_as_float(dreg[j0 + k]);
                float lamlo = bfbits2f((uint16_t)(l4[g] >> (16 * k)));
                acc += lamlo * qvp[k];                 // diagonal compensation
                float v = fmaxf(STEPC * (cvp[k] - acc), 0.f);
                if (masked) v *= avp[k];
                uint16_t hb = f2bfbits(v);
                oh[k] = hb;
                ol[k] = f2bfbits(v - bfbits2f(hb));
            }
            *(uint64_t*)((char*)ohi + tb + boff[g]) =
                (uint64_t)oh[0] | ((uint64_t)oh[1] << 16)
                | ((uint64_t)oh[2] << 32) | ((uint64_t)oh[3] << 48);
            *(uint64_t*)((char*)olo + tb + boff[g]) =
                (uint64_t)ol[0] | ((uint64_t)ol[1] << 16)
                | ((uint64_t)ol[2] << 32) | ((uint64_t)ol[3] << 48);
        }
    }

    GDC_LAUNCH();

    __syncthreads();
    if (wid == 0) { TC_RELINQ(); TC_DEALLOC(tmem, 256); }
#endif  // HAS_TCGEN05
}

// epilogue variants (cg1 peripheral GEMMs)
enum { E_C = 0, E_ACT, E_MSK, E_Z, E_OUT, E_Q };

// ---------------------------------------------------------------------------
// Generic cg1 tcgen05 GEMM (3-product), fused epilogues, optional PDL early.
//   E_Q writes Q' = acc - (1/step) I as B-image + fp32 diag vector (o32).
// ---------------------------------------------------------------------------
template <int EPI>
__global__ void __launch_bounds__(256, 1) tc_gemm(
    const __nv_bfloat16* __restrict__ Ahi, const __nv_bfloat16* __restrict__ Alo,
    const __nv_bfloat16* __restrict__ Bhi, const __nv_bfloat16* __restrict__ Blo,
    int nch,
    const float* __restrict__ v1, const float* __restrict__ v2,
    float* __restrict__ o32,
    __nv_bfloat16* __restrict__ ohi, __nv_bfloat16* __restrict__ olo,
    int Ncols, int early)
{
#if HAS_TCGEN05
    extern __shared__ char draw[];
    const uint32_t dsm = (s2u(draw) + 1023u) & ~1023u;

    __shared__ uint32_t s_tmem;
    __shared__ __align__(8) uint64_t s_bar[5];

    const int tid  = threadIdx.x;
    const int wid  = tid >> 5;
    const int lane = tid & 31;
    const int bm0  = blockIdx.y * TM;
    const int bn0  = blockIdx.x * TN;

    const uint32_t f0 = s2u(&s_bar[0]);
    const uint32_t f1 = s2u(&s_bar[1]);
    const uint32_t e0 = s2u(&s_bar[2]);
    const uint32_t e1 = s2u(&s_bar[3]);
    const uint32_t db = s2u(&s_bar[4]);

    if (wid == 0) TC_ALLOC(s2u(&s_tmem), 256);
    if (tid == 0) {
        mbar_init(f0, 1); mbar_init(f1, 1);
        mbar_init(e0, 1); mbar_init(e1, 1);
        mbar_init(db, 1);
    }
    __syncthreads();
    uint32_t tmem;
    asm volatile("ld.shared.b32 %0, [%1];" : "=r"(tmem) : "r"(s2u(&s_tmem)));

    const int earlyA = early & 1, earlyB = early & 2;
    const char* aH = (const char*)Ahi + (size_t)blockIdx.y * nch * TILEA_B;
    const char* aL = (const char*)Alo + (size_t)blockIdx.y * nch * TILEA_B;
    const char* bH = (const char*)Bhi + (size_t)blockIdx.x * nch * TILEB_B;
    const char* bL = (const char*)Blo + (size_t)blockIdx.x * nch * TILEB_B;

    if (tid == 0 && earlyB) {
#pragma unroll
        for (int ch = 0; ch < 2; ch++) {
            const uint32_t fb = ch ? f1 : f0;
            const uint32_t st = dsm + (uint32_t)ch * STG_SZ;
            mbar_tx_only(fb, 2 * TILEB_B);
            bulk_g2s(st + OFF_BHI, bH + (size_t)ch * TILEB_B, TILEB_B, fb);
            bulk_g2s(st + OFF_BLO, bL + (size_t)ch * TILEB_B, TILEB_B, fb);
        }
    }
    if (tid == 0 && earlyA) {
#pragma unroll
        for (int ch = 0; ch < 2; ch++) {
            const uint32_t fb = ch ? f1 : f0;
            const uint32_t st = dsm + (uint32_t)ch * STG_SZ;
            mbar_arrive_tx(fb, earlyB ? 2 * TILEA_B : (uint32_t)STG_SZ);
            bulk_g2s(st,           aH + (size_t)ch * TILEA_B, TILEA_B, fb);
            bulk_g2s(st + OFF_ALO, aL + (size_t)ch * TILEA_B, TILEA_B, fb);
            if (!earlyB) {
                bulk_g2s(st + OFF_BHI, bH + (size_t)ch * TILEB_B, TILEB_B, fb);
                bulk_g2s(st + OFF_BLO, bL + (size_t)ch * TILEB_B, TILEB_B, fb);
            }
        }
    }
    if (!earlyA) {
        GDC_WAIT();
        if (tid == 0) {
#pragma unroll
            for (int ch = 0; ch < 2; ch++) {
                const uint32_t fb = ch ? f1 : f0;
                const uint32_t st = dsm + (uint32_t)ch * STG_SZ;
                mbar_arrive_tx(fb, earlyB ? 2 * TILEA_B : (uint32_t)STG_SZ);
                bulk_g2s(st,           aH + (size_t)ch * TILEA_B, TILEA_B, fb);
                bulk_g2s(st + OFF_ALO, aL + (size_t)ch * TILEA_B, TILEA_B, fb);
                if (!earlyB) {
                    bulk_g2s(st + OFF_BHI, bH + (size_t)ch * TILEB_B, TILEB_B, fb);
                    bulk_g2s(st + OFF_BLO, bL + (size_t)ch * TILEB_B, TILEB_B, fb);
                }
            }
        }
    }

    if (tid == 0) {
        uint32_t phf[2] = {0, 0}, phe[2] = {0, 0};
#pragma unroll 1
        for (int ch = 0; ch < nch; ch++) {
            const int s = ch & 1;
            mbar_wait(s ? f1 : f0, phf[s]); phf[s] ^= 1;

            const uint32_t st = dsm + (uint32_t)s * STG_SZ;
            const uint64_t dah = mkdesc(st);
            const uint64_t dal = mkdesc(st + OFF_ALO);
            const uint64_t dbh = mkdesc(st + OFF_BHI);
            const uint64_t dbl = mkdesc(st + OFF_BLO);
#pragma unroll
            for (int ks = 0; ks < 4; ks++) {
                mma_f16_ss(tmem, dah + ks * 2, dbh + ks * 2, GEMM_IDESC,
                           (ch == 0 && ks == 0) ? 0u : 1u);
                mma_f16_ss(tmem, dah + ks * 2, dbl + ks * 2, GEMM_IDESC, 1u);
                mma_f16_ss(tmem, dal + ks * 2, dbh + ks * 2, GEMM_IDESC, 1u);
            }
            tc_commit(s ? e1 : e0);

            if (ch + 2 < nch) {
                mbar_wait(s ? e1 : e0, phe[s]); phe[s] ^= 1;
                const int nx = ch + 2;
                const uint32_t fb = s ? f1 : f0;
                const uint32_t st2 = dsm + (uint32_t)s * STG_SZ;
                mbar_arrive_tx(fb, (uint32_t)STG_SZ);
                bulk_g2s(st2,           aH + (size_t)nx * TILEA_B, TILEA_B, fb);
                bulk_g2s(st2 + OFF_ALO, aL + (size_t)nx * TILEA_B, TILEA_B, fb);
                bulk_g2s(st2 + OFF_BHI, bH + (size_t)nx * TILEB_B, TILEB_B, fb);
                bulk_g2s(st2 + OFF_BLO, bL + (size_t)nx * TILEB_B, TILEB_B, fb);
            }
        }
        tc_commit(db);
    }

    mbar_wait(db, 0);
    if (earlyA) GDC_WAIT();   // chain ordering before epilogue reads (e.g. act)
    TC_FENCE_AFTER();

    const int sp   = wid & 3;
    const int half = wid >> 2;
    const int lr   = sp * 32 + lane;
    const int r    = bm0 + lr;
    const int nchO = Ncols >> 6;

#pragma unroll 1
    for (int cb = 0; cb < 128; cb += 32) {
        uint32_t dreg[32];
        LDTM_X32(dreg, tmem + half * 128 + cb);
        TC_WAIT_LD();

        const int coff = half * 128 + cb;
        const int gch  = (bn0 + coff) >> 6;
        const int lc0  = coff & 63;
        const size_t blin = (size_t)r * Ncols + bn0 + coff;
        const size_t tbA = ((size_t)(blockIdx.y * nchO + gch)) * TILEA_B;
        const size_t tbB = ((size_t)((r >> 8) * nchO + gch)) * TILEB_B;
        const int brow = r & 255;

#pragma unroll
        for (int j0 = 0; j0 < 32; j0 += 4) {
            const uint32_t boffA = swz((uint32_t)(lr * 128 + (lc0 + j0) * 2));
            float res[4];
#pragma unroll
            for (int k = 0; k < 4; k++) res[k] = __uint_as_float(dreg[j0 + k]);

            if (EPI == E_C) {
                float4 bv = *(const float4*)&v1[bn0 + coff + j0];
                const float* bp = (const float*)&bv;
                uint16_t oh[4], ol[4];
                float cvv[4];
#pragma unroll
                for (int k = 0; k < 4; k++) {
                    float cv = res[k] - bp[k];
                    cvv[k] = cv;
                    float v = fmaxf(STEPC * cv, 0.f);
                    uint16_t hb = f2bfbits(v);
                    oh[k] = hb; ol[k] = f2bfbits(v - bfbits2f(hb));
                }
                *(float4*)&o32[blin + j0] = make_float4(cvv[0], cvv[1], cvv[2], cvv[3]);
                *(uint64_t*)((char*)ohi + tbA + boffA) =
                    (uint64_t)oh[0] | ((uint64_t)oh[1] << 16)
                    | ((uint64_t)oh[2] << 32) | ((uint64_t)oh[3] << 48);
                *(uint64_t*)((char*)olo + tbA + boffA) =
                    (uint64_t)ol[0] | ((uint64_t)ol[1] << 16)
                    | ((uint64_t)ol[2] << 32) | ((uint64_t)ol[3] << 48);
            } else if (EPI == E_ACT) {
                float4 bv = *(const float4*)&v1[bn0 + coff + j0];
                const float* bp = (const float*)&bv;
                float o[4];
#pragma unroll
                for (int k = 0; k < 4; k++)
                    o[k] = (res[k] >= bp[k] - TOLV) ? 1.f : 0.f;
                *(float4*)&o32[blin + j0] = make_float4(o[0], o[1], o[2], o[3]);
            } else if (EPI == E_MSK) {
                float4 avv = *(const float4*)&v1[blin + j0];
                const float* ap = (const float*)&avv;
                uint16_t oh[4], ol[4];
                float mm[4];
#pragma unroll
                for (int k = 0; k < 4; k++) {
                    float m = res[k] * ap[k];
                    mm[k] = m;
                    float v = fmaxf(STEPC * m, 0.f) * ap[k];
                    uint16_t hb = f2bfbits(v);
                    oh[k] = hb; ol[k] = f2bfbits(v - bfbits2f(hb));
                }
                *(float4*)&o32[blin + j0] = make_float4(mm[0], mm[1], mm[2], mm[3]);
                *(uint64_t*)((char*)ohi + tbA + boffA) =
                    (uint64_t)oh[0] | ((uint64_t)oh[1] << 16)
                    | ((uint64_t)oh[2] << 32) | ((uint64_t)oh[3] << 48);
                *(uint64_t*)((char*)olo + tbA + boffA) =
                    (uint64_t)ol[0] | ((uint64_t)ol[1] << 16)
                    | ((uint64_t)ol[2] << 32) | ((uint64_t)ol[3] << 48);
            } else if (EPI == E_Z) {
                float4 xv = *(const float4*)&v1[blin + j0];
                float4 uv = *(const float4*)&v2[blin + j0];
                const float* xp = (const float*)&xv;
                const float* up = (const float*)&uv;
                uint16_t oh[4], ol[4];
#pragma unroll
                for (int k = 0; k < 4; k++) {
                    float zv = xp[k] + up[k] - res[k];
                    uint16_t hb = f2bfbits(zv);
                    oh[k] = hb; ol[k] = f2bfbits(zv - bfbits2f(hb));
                }
                *(uint64_t*)((char*)ohi + tbA + boffA) =
                    (uint64_t)oh[0] | ((uint64_t)oh[1] << 16)
                    | ((uint64_t)oh[2] << 32) | ((uint64_t)oh[3] << 48);
                *(uint64_t*)((char*)olo + tbA + boffA) =
                    (uint64_t)ol[0] | ((uint64_t)ol[1] << 16)
                    | ((uint64_t)ol[2] << 32) | ((uint64_t)ol[3] << 48);
            } else if (EPI == E_OUT) {
                float4 uv = *(const float4*)&v1[blin + j0];
                const float* up = (const float*)&uv;
                float o[4];
#pragma unroll
                for (int k = 0; k < 4; k++) o[k] = up[k] - res[k];
                *(float4*)&o32[blin + j0] = make_float4(o[0], o[1], o[2], o[3]);
            } else if (EPI == E_Q) {
                const uint32_t boffB = swz((uint32_t)(brow * 128 + (lc0 + j0) * 2));
                uint16_t oh[4], ol[4];
#pragma unroll
                for (int k = 0; k < 4; k++) {
                    float qv = res[k];
                    if (r == bn0 + coff + j0 + k) {
                        qv -= INVSTEP;           // Q' = Q - (1/step) I
                        o32[r] = qv;             // fp32 diag vector
                    }
                    uint16_t hb = f2bfbits(qv);
                    oh[k] = hb; ol[k] = f2bfbits(qv - bfbits2f(hb));
                }
                *(uint64_t*)((char*)ohi + tbB + boffB) =
                    (uint64_t)oh[0] | ((uint64_t)oh[1] << 16)
                    | ((uint64_t)oh[2] << 32) | ((uint64_t)oh[3] << 48);
                *(uint64_t*)((char*)olo + tbB + boffB) =
                    (uint64_t)ol[0] | ((uint64_t)ol[1] << 16)
                    | ((uint64_t)ol[2] << 32) | ((uint64_t)ol[3] << 48);
            }
        }
    }

    GDC_LAUNCH();

    __syncthreads();
    if (wid == 0) { TC_RELINQ(); TC_DEALLOC(tmem, 256); }
#endif  // HAS_TCGEN05
}

// ---------------- prep kernels ----------------
__device__ __forceinline__ void img_store(__nv_bfloat16* hi, __nv_bfloat16* lo,
                                          size_t tb, uint32_t boff, float v)
{
    __nv_bfloat16 h = __float2bfloat16(v);
    *(__nv_bfloat16*)((char*)hi + tb + boff) = h;
    *(__nv_bfloat16*)((char*)lo + tb + boff) = __float2bfloat16(v - __bfloat162float(h));
}

__global__ void split_A_images(const float* __restrict__ A)
{
    int i = blockIdx.x * blockDim.x + threadIdx.x;
    if (i >= Mm * Nn) return;
    int r = i >> 9, k = i & 511;
    float v = A[i];
    int ch = k >> 6, lc = k & 63;
    {
        int bm = r >> 7, lrow = r & 127;
        size_t tb = ((size_t)(bm * 8 + ch)) * TILEA_B;
        img_store(g_AAi_h, g_AAi_l, tb, swz((uint32_t)(lrow * 128 + lc * 2)), v);
    }
    {
        int nb = r >> 8, brow = r & 255;
        size_t tb = ((size_t)(nb * 8 + ch)) * TILEB_B;
        img_store(g_ABi_h, g_ABi_l, tb, swz((uint32_t)(brow * 128 + lc * 2)), v);
    }
}

__global__ void split_AT_image(const float* __restrict__ A)
{
    int i = blockIdx.x * blockDim.x + threadIdx.x;
    if (i >= Nn * Mm) return;
    int n = i >> 10, k = i & 1023;
    float v = A[(size_t)k * Nn + n];
    int nb = n >> 8, brow = n & 255, ch = k >> 6, lc = k & 63;
    size_t tb = ((size_t)(nb * 16 + ch)) * TILEB_B;
    img_store(g_ATi_h, g_ATi_l, tb, swz((uint32_t)(brow * 128 + lc * 2)), v);
}

__global__ void split_xu_u(const float* __restrict__ x, const float* __restrict__ u)
{
    int i = blockIdx.x * blockDim.x + threadIdx.x;
    if (i >= Bsz * Nn) return;
    int r = i >> 9, k = i & 511;
    int bm = r >> 7, lrow = r & 127, ch = k >> 6, lc = k & 63;
    size_t tb = ((size_t)(bm * 8 + ch)) * TILEA_B;
    uint32_t boff = swz((uint32_t)(lrow * 128 + lc * 2));
    float uv = u[i];
    img_store(g_xu_h, g_xu_l, tb, boff, x[i] + uv);
    img_store(g_u_h,  g_u_l,  tb, boff, uv);
}

// ---------------------------------------------------------------------------
extern "C" void kernel_launch(void* const* d_in, const int* in_sizes, int n_in,
                              void* d_out, int out_size)
{
    const float* x = (const float*)d_in[0];
    const float* u = (const float*)d_in[1];
    const float* A = (const float*)d_in[2];
    const float* b = (const float*)d_in[3];
    float* out = (float*)d_out;

    float *c, *msk, *act, *qdg;
    __nv_bfloat16 *AAh, *AAl, *ABh, *ABl, *ATh, *ATl, *XUh, *XUl, *Uh, *Ul,
                  *Zh, *Zl, *Qh, *Ql, *lAh, *lAl, *lBh, *lBl;
    cudaGetSymbolAddress((void**)&c,   g_c);
    cudaGetSymbolAddress((void**)&msk, g_msk);
    cudaGetSymbolAddress((void**)&act, g_act);
    cudaGetSymbolAddress((void**)&qdg, g_qdiag);
    cudaGetSymbolAddress((void**)&AAh, g_AAi_h); cudaGetSymbolAddress((void**)&AAl, g_AAi_l);
    cudaGetSymbolAddress((void**)&ABh, g_ABi_h); cudaGetSymbolAddress((void**)&ABl, g_ABi_l);
    cudaGetSymbolAddress((void**)&ATh, g_ATi_h); cudaGetSymbolAddress((void**)&ATl, g_ATi_l);
    cudaGetSymbolAddress((void**)&XUh, g_xu_h);  cudaGetSymbolAddress((void**)&XUl, g_xu_l);
    cudaGetSymbolAddress((void**)&Uh,  g_u_h);   cudaGetSymbolAddress((void**)&Ul,  g_u_l);
    cudaGetSymbolAddress((void**)&Zh,  g_z_h);   cudaGetSymbolAddress((void**)&Zl,  g_z_l);
    cudaGetSymbolAddress((void**)&Qh,  g_Qhi);   cudaGetSymbolAddress((void**)&Ql,  g_Qlo);
    cudaGetSymbolAddress((void**)&lAh, g_lAhi);  cudaGetSymbolAddress((void**)&lAl, g_lAlo);
    cudaGetSymbolAddress((void**)&lBh, g_lBhi);  cudaGetSymbolAddress((void**)&lBl, g_lBlo);

    cudaFuncSetAttribute(tc_gemm<E_C>,   cudaFuncAttributeMaxDynamicSharedMemorySize, DSMEM);
    cudaFuncSetAttribute(tc_gemm<E_ACT>, cudaFuncAttributeMaxDynamicSharedMemorySize, DSMEM);
    cudaFuncSetAttribute(tc_gemm<E_MSK>, cudaFuncAttributeMaxDynamicSharedMemorySize, DSMEM);
    cudaFuncSetAttribute(tc_gemm<E_Z>,   cudaFuncAttributeMaxDynamicSharedMemorySize, DSMEM);
    cudaFuncSetAttribute(tc_gemm<E_OUT>, cudaFuncAttributeMaxDynamicSharedMemorySize, DSMEM);
    cudaFuncSetAttribute(tc_gemm<E_Q>,   cudaFuncAttributeMaxDynamicSharedMemorySize, DSMEM);
    cudaFuncSetAttribute(pgd_pdl,        cudaFuncAttributeMaxDynamicSharedMemorySize, DSMEM2);

    const dim3 blk(256);
    const int EW = 256;

    // prep (plain launches — first in chain)
    split_A_images<<<(Mm * Nn + EW - 1) / EW, EW>>>(A);
    split_AT_image<<<(Nn * Mm + EW - 1) / EW, EW>>>(A);
    split_xu_u<<<(int)(((size_t)Bsz * Nn + EW - 1) / EW), EW>>>(x, u);

    // PDL config (grid mutated per launch)
    cudaLaunchAttribute pdlAttr;
    pdlAttr.id = cudaLaunchAttributeProgrammaticStreamSerialization;
    pdlAttr.val.programmaticStreamSerializationAllowed = 1;
    cudaLaunchConfig_t cfg = {};
    cfg.blockDim = blk;
    cfg.dynamicSmemBytes = DSMEM;
    cfg.stream = 0;
    cfg.attrs = &pdlAttr;
    cfg.numAttrs = 1;

    // Q' = A @ A^T - (1/step) I -> Q B-images + diag vector
    cfg.gridDim = dim3(4, 8);
    cudaLaunchKernelEx(&cfg, tc_gemm<E_Q>,
                       (const __nv_bfloat16*)AAh, (const __nv_bfloat16*)AAl,
                       (const __nv_bfloat16*)ABh, (const __nv_bfloat16*)ABl, 8,
                       (const float*)nullptr, (const float*)nullptr,
                       qdg, Qh, Ql, 1024, 0);

    // c = xu @ A^T - b (+ lam init): operands from prep -> early=3
    cfg.gridDim = dim3(4, 32);
    cudaLaunchKernelEx(&cfg, tc_gemm<E_C>,
                       (const __nv_bfloat16*)XUh, (const __nv_bfloat16*)XUl,
                       (const __nv_bfloat16*)ABh, (const __nv_bfloat16*)ABl, 8,
                       (const float*)b, (const float*)nullptr,
                       c, lAh, lAl, 1024, 3);

    // PGD iters 2..50 (49 PDL launches, folded Q', 2-product + compensation)
    cudaLaunchConfig_t cfgP = cfg;
    cfgP.dynamicSmemBytes = DSMEM2;
    cfgP.gridDim = dim3(4, 32);
    __nv_bfloat16 *curh = lAh, *curl = lAl, *nxth = lBh, *nxtl = lBl;
    for (int it = 1; it < 50; it++) {
        cudaLaunchKernelEx(&cfgP, pgd_pdl,
                           (const __nv_bfloat16*)curh, (const __nv_bfloat16*)curl,
                           (const __nv_bfloat16*)Qh,  (const __nv_bfloat16*)Ql,
                           (const float*)c, (const float*)nullptr, (const float*)qdg,
                           nxth, nxtl, 0);
        __nv_bfloat16* t;
        t = curh; curh = nxth; nxth = t;
        t = curl; curl = nxtl; nxtl = t;
    }

    // z = x + u - lam @ A  (A = lam from pred -> earlyB only)
    cfg.gridDim = dim3(2, 32);
    cudaLaunchKernelEx(&cfg, tc_gemm<E_Z>,
                       (const __nv_bfloat16*)curh, (const __nv_bfloat16*)curl,
                       (const __nv_bfloat16*)ATh, (const __nv_bfloat16*)ATl, 16,
                       (const float*)x, (const float*)u,
                       (float*)nullptr, Zh, Zl, 512, 2);
    // active  (A = z from pred -> earlyB only)
    cfg.gridDim = dim3(4, 32);
    cudaLaunchKernelEx(&cfg, tc_gemm<E_ACT>,
                       (const __nv_bfloat16*)Zh, (const __nv_bfloat16*)Zl,
                       (const __nv_bfloat16*)ABh, (const __nv_bfloat16*)ABl, 8,
                       (const float*)b, (const float*)nullptr,
                       act, (__nv_bfloat16*)nullptr, (__nv_bfloat16*)nullptr, 1024, 2);
    // masked (+ masked lam init): both operands prep-constant -> early=3
    cfg.gridDim = dim3(4, 32);
    cudaLaunchKernelEx(&cfg, tc_gemm<E_MSK>,
                       (const __nv_bfloat16*)Uh, (const __nv_bfloat16*)Ul,
                       (const __nv_bfloat16*)ABh, (const __nv_bfloat16*)ABl, 8,
                       (const float*)act, (const float*)nullptr,
                       msk, lAh, lAl, 1024, 3);

    // masked PGD iters 2..10 (9 PDL launches)
    curh = lAh; curl = lAl; nxth = lBh; nxtl = lBl;
    for (int it = 1; it < 10; it++) {
        cudaLaunchKernelEx(&cfgP, pgd_pdl,
                           (const __nv_bfloat16*)curh, (const __nv_bfloat16*)curl,
                           (const __nv_bfloat16*)Qh,  (const __nv_bfloat16*)Ql,
                           (const float*)msk, (const float*)act, (const float*)qdg,
                           nxth, nxtl, 1);
        __nv_bfloat16* t;
        t = curh; curh = nxth; nxth = t;
        t = curl; curl = nxtl; nxtl = t;
    }

    // out = u - lam @ A  (A = lam from pred -> earlyB only)
    cfg.gridDim = dim3(2, 32);
    cudaLaunchKernelEx(&cfg, tc_gemm<E_OUT>,
                       (const __nv_bfloat16*)curh, (const __nv_bfloat16*)curl,
                       (const __nv_bfloat16*)ATh, (const __nv_bfloat16*)ATl, 16,
                       (const float*)u, (const float*)nullptr,
                       out, (__nv_bfloat16*)nullptr, (__nv_bfloat16*)nullptr, 512, 2);
}